// round 4
// baseline (speedup 1.0000x reference)
#include <cuda_runtime.h>
#include <math.h>

#define Bsz 8
#define Sq  512
#define Dm  768
#define Hn  12
#define HDm 64
#define En  8
#define FFd 3072
#define TOK 4096
#define BHN 96

// ---------------- scratch (device globals; no allocations allowed) ----------
__device__ float g_h[TOK * Dm];
__device__ float g_qkv[TOK * 3 * Dm];
__device__ float g_scores[(size_t)BHN * Sq * Sq];
__device__ float g_o[TOK * Dm];
__device__ float g_h2[TOK * Dm];
__device__ float g_y1[(size_t)TOK * FFd];
__device__ int   g_routes[TOK];
__device__ int   g_cnt[En];
__device__ int   g_off[En];
__device__ int   g_cur[En];
__device__ int   g_sorted[TOK];

// ---------------- helpers ---------------------------------------------------
__device__ __forceinline__ float gelu_exact(float x) {
    return 0.5f * x * (1.0f + erff(x * 0.70710678118654752f));
}

__device__ __forceinline__ unsigned f2t(float f) {
    unsigned u;
    asm("cvt.rna.tf32.f32 %0, %1;" : "=r"(u) : "f"(f));
    return u;
}
__device__ __forceinline__ uint4 cvt4(float4 v) {
    return make_uint4(f2t(v.x), f2t(v.y), f2t(v.z), f2t(v.w));
}

__device__ __forceinline__ void mma_tf32(float c[4],
                                         unsigned a0, unsigned a1, unsigned a2, unsigned a3,
                                         unsigned b0, unsigned b1) {
    asm volatile(
        "mma.sync.aligned.m16n8k8.row.col.f32.tf32.tf32.f32 "
        "{%0,%1,%2,%3},{%4,%5,%6,%7},{%8,%9},{%0,%1,%2,%3};"
        : "+f"(c[0]), "+f"(c[1]), "+f"(c[2]), "+f"(c[3])
        : "r"(a0), "r"(a1), "r"(a2), "r"(a3), "r"(b0), "r"(b1));
}

// ---------------- reset counters --------------------------------------------
__global__ void reset_kernel() {
    int t = threadIdx.x;
    if (t < En) { g_cnt[t] = 0; g_cur[t] = 0; }
}

// ---------------- layernorm: one block (256 thr) per row of 768 -------------
__global__ void ln_kernel(const float* __restrict__ X,
                          const float* __restrict__ gam,
                          const float* __restrict__ bet,
                          float* __restrict__ Y) {
    int row = blockIdx.x;
    int tid = threadIdx.x;
    const float* x = X + (size_t)row * Dm;
    float v0 = x[tid], v1 = x[tid + 256], v2 = x[tid + 512];

    __shared__ float red[256];
    float s = v0 + v1 + v2;
    red[tid] = s; __syncthreads();
    #pragma unroll
    for (int st = 128; st > 0; st >>= 1) {
        if (tid < st) red[tid] += red[tid + st];
        __syncthreads();
    }
    float mu = red[0] / (float)Dm;
    __syncthreads();

    float d0 = v0 - mu, d1 = v1 - mu, d2 = v2 - mu;
    float q = d0 * d0 + d1 * d1 + d2 * d2;
    red[tid] = q; __syncthreads();
    #pragma unroll
    for (int st = 128; st > 0; st >>= 1) {
        if (tid < st) red[tid] += red[tid + st];
        __syncthreads();
    }
    float rstd = rsqrtf(red[0] / (float)Dm + 1e-5f);

    float* y = Y + (size_t)row * Dm;
    y[tid]       = d0 * rstd * gam[tid]       + bet[tid];
    y[tid + 256] = d1 * rstd * gam[tid + 256] + bet[tid + 256];
    y[tid + 512] = d2 * rstd * gam[tid + 512] + bet[tid + 512];
}

// =============================================================================
// Generic tf32 tensor-core GEMM: C = A@B (+bias)(+resid)
// BM=128, BN=128, BK=16, 256 threads = 8 warps (2x4), warp tile 64x32.
// As: row-major [m][k], stride 20 (20 mod 32 = 20, frag banks 20m+tg distinct).
// Bs: row-major [k][n], stride 136 (mod 32 = 8, frag banks 8k+gid distinct).
// =============================================================================
#define ASTR 20
#define BSTR 136

__global__ void gemm_tf32(const float* __restrict__ A, const float* __restrict__ B,
                          float* __restrict__ C, int M, int N, int K,
                          const float* __restrict__ bias,
                          const float* __restrict__ resid) {
    __shared__ unsigned As[128 * ASTR];
    __shared__ unsigned Bs[16 * BSTR];
    int tid = threadIdx.x;
    int warp = tid >> 5, lane = tid & 31;
    int gid = lane >> 2, tg = lane & 3;
    int wm = (warp >> 2) * 64, wn = (warp & 3) * 32;
    int m0 = blockIdx.y * 128, n0 = blockIdx.x * 128;

    float acc[4][4][4];
    #pragma unroll
    for (int i = 0; i < 4; i++)
        #pragma unroll
        for (int j = 0; j < 4; j++)
            #pragma unroll
            for (int q = 0; q < 4; q++) acc[i][j][q] = 0.f;

    for (int k0 = 0; k0 < K; k0 += 16) {
        #pragma unroll
        for (int l = 0; l < 2; l++) {
            int idx = tid + l * 256, r = idx >> 2, c4 = (idx & 3) * 4;
            float4 v = *(const float4*)(A + (size_t)(m0 + r) * K + k0 + c4);
            *(uint4*)&As[r * ASTR + c4] = cvt4(v);
        }
        #pragma unroll
        for (int l = 0; l < 2; l++) {
            int idx = tid + l * 256, r = idx >> 5, c4 = (idx & 31) * 4;
            float4 v = *(const float4*)(B + (size_t)(k0 + r) * N + n0 + c4);
            *(uint4*)&Bs[r * BSTR + c4] = cvt4(v);
        }
        __syncthreads();
        #pragma unroll
        for (int ks = 0; ks < 2; ks++) {
            int kb = ks * 8;
            unsigned af[4][4], bf[4][2];
            #pragma unroll
            for (int mt = 0; mt < 4; mt++) {
                int m = wm + mt * 16 + gid;
                af[mt][0] = As[m * ASTR + kb + tg];
                af[mt][1] = As[(m + 8) * ASTR + kb + tg];
                af[mt][2] = As[m * ASTR + kb + tg + 4];
                af[mt][3] = As[(m + 8) * ASTR + kb + tg + 4];
            }
            #pragma unroll
            for (int nt = 0; nt < 4; nt++) {
                int n = wn + nt * 8 + gid;
                bf[nt][0] = Bs[(kb + tg) * BSTR + n];
                bf[nt][1] = Bs[(kb + tg + 4) * BSTR + n];
            }
            #pragma unroll
            for (int mt = 0; mt < 4; mt++)
                #pragma unroll
                for (int nt = 0; nt < 4; nt++)
                    mma_tf32(acc[mt][nt], af[mt][0], af[mt][1], af[mt][2], af[mt][3],
                             bf[nt][0], bf[nt][1]);
        }
        __syncthreads();
    }
    #pragma unroll
    for (int mt = 0; mt < 4; mt++) {
        int mA = m0 + wm + mt * 16 + gid, mB = mA + 8;
        #pragma unroll
        for (int nt = 0; nt < 4; nt++) {
            int n = n0 + wn + nt * 8 + tg * 2;
            float v0 = acc[mt][nt][0], v1 = acc[mt][nt][1];
            float v2 = acc[mt][nt][2], v3 = acc[mt][nt][3];
            if (bias) {
                float b0 = bias[n], b1 = bias[n + 1];
                v0 += b0; v1 += b1; v2 += b0; v3 += b1;
            }
            if (resid) {
                v0 += resid[(size_t)mA * N + n];
                v1 += resid[(size_t)mA * N + n + 1];
                v2 += resid[(size_t)mB * N + n];
                v3 += resid[(size_t)mB * N + n + 1];
            }
            C[(size_t)mA * N + n]     = v0;
            C[(size_t)mA * N + n + 1] = v1;
            C[(size_t)mB * N + n]     = v2;
            C[(size_t)mB * N + n + 1] = v3;
        }
    }
}

// ---------------- MoE GEMM1 (tf32): Y1 = gelu(gather(H2) @ W1[e] + b1[e]) ----
__global__ void moe1_tf32(const float* __restrict__ H2,
                          const float* __restrict__ W1,
                          const float* __restrict__ B1,
                          float* __restrict__ Y1) {
    int e = blockIdx.z;
    int cnt = g_cnt[e];
    int m0 = blockIdx.y * 128;
    if (m0 >= cnt) return;
    int off = g_off[e];
    const float* B = W1 + (size_t)e * Dm * FFd;
    const int N = FFd, K = Dm;
    int n0 = blockIdx.x * 128;

    __shared__ unsigned As[128 * ASTR];
    __shared__ unsigned Bs[16 * BSTR];
    __shared__ int toks[128];
    int tid = threadIdx.x;
    int warp = tid >> 5, lane = tid & 31;
    int gid = lane >> 2, tg = lane & 3;
    int wm = (warp >> 2) * 64, wn = (warp & 3) * 32;
    if (tid < 128) {
        int m = m0 + tid;
        toks[tid] = (m < cnt) ? g_sorted[off + m] : -1;
    }
    __syncthreads();

    float acc[4][4][4];
    #pragma unroll
    for (int i = 0; i < 4; i++)
        #pragma unroll
        for (int j = 0; j < 4; j++)
            #pragma unroll
            for (int q = 0; q < 4; q++) acc[i][j][q] = 0.f;

    for (int k0 = 0; k0 < K; k0 += 16) {
        #pragma unroll
        for (int l = 0; l < 2; l++) {
            int idx = tid + l * 256, r = idx >> 2, c4 = (idx & 3) * 4;
            int tok = toks[r];
            float4 v = make_float4(0.f, 0.f, 0.f, 0.f);
            if (tok >= 0)
                v = *(const float4*)(H2 + (size_t)tok * Dm + k0 + c4);
            *(uint4*)&As[r * ASTR + c4] = cvt4(v);
        }
        #pragma unroll
        for (int l = 0; l < 2; l++) {
            int idx = tid + l * 256, r = idx >> 5, c4 = (idx & 31) * 4;
            float4 v = *(const float4*)(B + (size_t)(k0 + r) * N + n0 + c4);
            *(uint4*)&Bs[r * BSTR + c4] = cvt4(v);
        }
        __syncthreads();
        #pragma unroll
        for (int ks = 0; ks < 2; ks++) {
            int kb = ks * 8;
            unsigned af[4][4], bf[4][2];
            #pragma unroll
            for (int mt = 0; mt < 4; mt++) {
                int m = wm + mt * 16 + gid;
                af[mt][0] = As[m * ASTR + kb + tg];
                af[mt][1] = As[(m + 8) * ASTR + kb + tg];
                af[mt][2] = As[m * ASTR + kb + tg + 4];
                af[mt][3] = As[(m + 8) * ASTR + kb + tg + 4];
            }
            #pragma unroll
            for (int nt = 0; nt < 4; nt++) {
                int n = wn + nt * 8 + gid;
                bf[nt][0] = Bs[(kb + tg) * BSTR + n];
                bf[nt][1] = Bs[(kb + tg + 4) * BSTR + n];
            }
            #pragma unroll
            for (int mt = 0; mt < 4; mt++)
                #pragma unroll
                for (int nt = 0; nt < 4; nt++)
                    mma_tf32(acc[mt][nt], af[mt][0], af[mt][1], af[mt][2], af[mt][3],
                             bf[nt][0], bf[nt][1]);
        }
        __syncthreads();
    }
    #pragma unroll
    for (int mt = 0; mt < 4; mt++) {
        int lmA = wm + mt * 16 + gid;
        int gmA = m0 + lmA, gmB = gmA + 8;
        #pragma unroll
        for (int nt = 0; nt < 4; nt++) {
            int n = wn + nt * 8 + tg * 2;
            float b0 = B1[e * FFd + n0 + n], b1 = B1[e * FFd + n0 + n + 1];
            if (gmA < cnt) {
                Y1[(size_t)(off + gmA) * FFd + n0 + n]     = gelu_exact(acc[mt][nt][0] + b0);
                Y1[(size_t)(off + gmA) * FFd + n0 + n + 1] = gelu_exact(acc[mt][nt][1] + b1);
            }
            if (gmB < cnt) {
                Y1[(size_t)(off + gmB) * FFd + n0 + n]     = gelu_exact(acc[mt][nt][2] + b0);
                Y1[(size_t)(off + gmB) * FFd + n0 + n + 1] = gelu_exact(acc[mt][nt][3] + b1);
            }
        }
    }
}

// ---------------- MoE GEMM2 (tf32): out[t] += gelu(Y1 @ W2[e] + b2[e]) ------
__global__ void moe2_tf32(const float* __restrict__ Y1,
                          const float* __restrict__ W2,
                          const float* __restrict__ B2,
                          float* __restrict__ OUT) {
    int e = blockIdx.z;
    int cnt = g_cnt[e];
    int m0 = blockIdx.y * 128;
    if (m0 >= cnt) return;
    int off = g_off[e];
    const float* B = W2 + (size_t)e * FFd * Dm;
    const int N = Dm, K = FFd;
    int n0 = blockIdx.x * 128;

    __shared__ unsigned As[128 * ASTR];
    __shared__ unsigned Bs[16 * BSTR];
    __shared__ int toks[128];
    int tid = threadIdx.x;
    int warp = tid >> 5, lane = tid & 31;
    int gid = lane >> 2, tg = lane & 3;
    int wm = (warp >> 2) * 64, wn = (warp & 3) * 32;
    if (tid < 128) {
        int m = m0 + tid;
        toks[tid] = (m < cnt) ? g_sorted[off + m] : -1;
    }
    __syncthreads();

    float acc[4][4][4];
    #pragma unroll
    for (int i = 0; i < 4; i++)
        #pragma unroll
        for (int j = 0; j < 4; j++)
            #pragma unroll
            for (int q = 0; q < 4; q++) acc[i][j][q] = 0.f;

    for (int k0 = 0; k0 < K; k0 += 16) {
        #pragma unroll
        for (int l = 0; l < 2; l++) {
            int idx = tid + l * 256, r = idx >> 2, c4 = (idx & 3) * 4;
            float4 v = make_float4(0.f, 0.f, 0.f, 0.f);
            if (m0 + r < cnt)
                v = *(const float4*)(Y1 + (size_t)(off + m0 + r) * FFd + k0 + c4);
            *(uint4*)&As[r * ASTR + c4] = cvt4(v);
        }
        #pragma unroll
        for (int l = 0; l < 2; l++) {
            int idx = tid + l * 256, r = idx >> 5, c4 = (idx & 31) * 4;
            float4 v = *(const float4*)(B + (size_t)(k0 + r) * N + n0 + c4);
            *(uint4*)&Bs[r * BSTR + c4] = cvt4(v);
        }
        __syncthreads();
        #pragma unroll
        for (int ks = 0; ks < 2; ks++) {
            int kb = ks * 8;
            unsigned af[4][4], bf[4][2];
            #pragma unroll
            for (int mt = 0; mt < 4; mt++) {
                int m = wm + mt * 16 + gid;
                af[mt][0] = As[m * ASTR + kb + tg];
                af[mt][1] = As[(m + 8) * ASTR + kb + tg];
                af[mt][2] = As[m * ASTR + kb + tg + 4];
                af[mt][3] = As[(m + 8) * ASTR + kb + tg + 4];
            }
            #pragma unroll
            for (int nt = 0; nt < 4; nt++) {
                int n = wn + nt * 8 + gid;
                bf[nt][0] = Bs[(kb + tg) * BSTR + n];
                bf[nt][1] = Bs[(kb + tg + 4) * BSTR + n];
            }
            #pragma unroll
            for (int mt = 0; mt < 4; mt++)
                #pragma unroll
                for (int nt = 0; nt < 4; nt++)
                    mma_tf32(acc[mt][nt], af[mt][0], af[mt][1], af[mt][2], af[mt][3],
                             bf[nt][0], bf[nt][1]);
        }
        __syncthreads();
    }
    #pragma unroll
    for (int mt = 0; mt < 4; mt++) {
        int lmA = wm + mt * 16 + gid;
        int gmA = m0 + lmA, gmB = gmA + 8;
        int tA = toks[lmA], tB = toks[lmA + 8];
        #pragma unroll
        for (int nt = 0; nt < 4; nt++) {
            int n = wn + nt * 8 + tg * 2;
            float b0 = B2[e * Dm + n0 + n], b1 = B2[e * Dm + n0 + n + 1];
            if (gmA < cnt) {
                OUT[(size_t)tA * Dm + n0 + n]     += gelu_exact(acc[mt][nt][0] + b0);
                OUT[(size_t)tA * Dm + n0 + n + 1] += gelu_exact(acc[mt][nt][1] + b1);
            }
            if (gmB < cnt) {
                OUT[(size_t)tB * Dm + n0 + n]     += gelu_exact(acc[mt][nt][2] + b0);
                OUT[(size_t)tB * Dm + n0 + n + 1] += gelu_exact(acc[mt][nt][3] + b1);
            }
        }
    }
}

// ---------------- scores (tf32 mma): S = scale * Q @ K^T --------------------
// 64x64 tile, K=64 all resident. Qs [m][k] str 68, Ks [n][k] str 68.
#define QSTR 68
__global__ void scores_tf32(const float* __restrict__ QKV,
                            float* __restrict__ S) {
    int bh = blockIdx.z;
    int b = bh / Hn, h = bh % Hn;
    int m0 = blockIdx.y * 64, n0 = blockIdx.x * 64;
    __shared__ unsigned Qs[64 * QSTR];
    __shared__ unsigned Ks[64 * QSTR];
    int tid = threadIdx.x;
    int warp = tid >> 5, lane = tid & 31;
    int gid = lane >> 2, tg = lane & 3;
    int wm = (warp >> 2) * 32, wn = (warp & 3) * 16;

    #pragma unroll
    for (int l = 0; l < 4; l++) {
        int idx = tid + l * 256, r = idx >> 4, c4 = (idx & 15) * 4;
        float4 q = *(const float4*)(QKV + (size_t)(b * Sq + m0 + r) * 2304 + h * HDm + c4);
        *(uint4*)&Qs[r * QSTR + c4] = cvt4(q);
        float4 k = *(const float4*)(QKV + (size_t)(b * Sq + n0 + r) * 2304 + Dm + h * HDm + c4);
        *(uint4*)&Ks[r * QSTR + c4] = cvt4(k);
    }
    __syncthreads();

    float acc[2][2][4];
    #pragma unroll
    for (int i = 0; i < 2; i++)
        #pragma unroll
        for (int j = 0; j < 2; j++)
            #pragma unroll
            for (int q = 0; q < 4; q++) acc[i][j][q] = 0.f;

    #pragma unroll
    for (int kb = 0; kb < 64; kb += 8) {
        unsigned af[2][4], bf[2][2];
        #pragma unroll
        for (int mt = 0; mt < 2; mt++) {
            int m = wm + mt * 16 + gid;
            af[mt][0] = Qs[m * QSTR + kb + tg];
            af[mt][1] = Qs[(m + 8) * QSTR + kb + tg];
            af[mt][2] = Qs[m * QSTR + kb + tg + 4];
            af[mt][3] = Qs[(m + 8) * QSTR + kb + tg + 4];
        }
        #pragma unroll
        for (int nt = 0; nt < 2; nt++) {
            int n = wn + nt * 8 + gid;
            bf[nt][0] = Ks[n * QSTR + kb + tg];
            bf[nt][1] = Ks[n * QSTR + kb + tg + 4];
        }
        #pragma unroll
        for (int mt = 0; mt < 2; mt++)
            #pragma unroll
            for (int nt = 0; nt < 2; nt++)
                mma_tf32(acc[mt][nt], af[mt][0], af[mt][1], af[mt][2], af[mt][3],
                         bf[nt][0], bf[nt][1]);
    }

    const float scale = 0.125f;
    #pragma unroll
    for (int mt = 0; mt < 2; mt++) {
        int mA = m0 + wm + mt * 16 + gid, mB = mA + 8;
        #pragma unroll
        for (int nt = 0; nt < 2; nt++) {
            int n = n0 + wn + nt * 8 + tg * 2;
            size_t pA = ((size_t)bh * Sq + mA) * Sq + n;
            size_t pB = ((size_t)bh * Sq + mB) * Sq + n;
            S[pA]     = acc[mt][nt][0] * scale;
            S[pA + 1] = acc[mt][nt][1] * scale;
            S[pB]     = acc[mt][nt][2] * scale;
            S[pB + 1] = acc[mt][nt][3] * scale;
        }
    }
}

// ---------------- row softmax over 512 --------------------------------------
__global__ void softmax_kernel(float* __restrict__ S) {
    size_t row = blockIdx.x;
    int tid = threadIdx.x;
    float* p = S + row * Sq;
    float v0 = p[tid], v1 = p[tid + 256];

    __shared__ float red[256];
    float m = fmaxf(v0, v1);
    red[tid] = m; __syncthreads();
    #pragma unroll
    for (int st = 128; st > 0; st >>= 1) {
        if (tid < st) red[tid] = fmaxf(red[tid], red[tid + st]);
        __syncthreads();
    }
    m = red[0]; __syncthreads();

    float e0 = __expf(v0 - m), e1 = __expf(v1 - m);
    red[tid] = e0 + e1; __syncthreads();
    #pragma unroll
    for (int st = 128; st > 0; st >>= 1) {
        if (tid < st) red[tid] += red[tid + st];
        __syncthreads();
    }
    float inv = 1.0f / red[0];
    p[tid] = e0 * inv;
    p[tid + 256] = e1 * inv;
}

// ---------------- O = P @ V  (tf32 mma) --------------------------------------
// Ps [m][k] str 36 (stage 64x32), Vs [k][n] str 72 (32x64).
#define PSTR 36
#define VSTR 72
__global__ void av_tf32(const float* __restrict__ S,
                        const float* __restrict__ QKV,
                        float* __restrict__ O) {
    int bh = blockIdx.y;
    int b = bh / Hn, h = bh % Hn;
    int m0 = blockIdx.x * 64;
    __shared__ unsigned Ps[64 * PSTR];
    __shared__ unsigned Vs[32 * VSTR];
    int tid = threadIdx.x;
    int warp = tid >> 5, lane = tid & 31;
    int gid = lane >> 2, tg = lane & 3;
    int wm = (warp >> 2) * 32, wn = (warp & 3) * 16;

    float acc[2][2][4];
    #pragma unroll
    for (int i = 0; i < 2; i++)
        #pragma unroll
        for (int j = 0; j < 2; j++)
            #pragma unroll
            for (int q = 0; q < 4; q++) acc[i][j][q] = 0.f;

    for (int k0 = 0; k0 < Sq; k0 += 32) {
        #pragma unroll
        for (int l = 0; l < 2; l++) {
            int idx = tid + l * 256, r = idx >> 3, c4 = (idx & 7) * 4;
            float4 v = *(const float4*)(S + ((size_t)bh * Sq + m0 + r) * Sq + k0 + c4);
            *(uint4*)&Ps[r * PSTR + c4] = cvt4(v);
        }
        #pragma unroll
        for (int l = 0; l < 2; l++) {
            int idx = tid + l * 256, r = idx >> 4, c4 = (idx & 15) * 4;
            float4 v = *(const float4*)(QKV + (size_t)(b * Sq + k0 + r) * 2304 + 2 * Dm + h * HDm + c4);
            *(uint4*)&Vs[r * VSTR + c4] = cvt4(v);
        }
        __syncthreads();
        #pragma unroll
        for (int kb = 0; kb < 32; kb += 8) {
            unsigned af[2][4], bf[2][2];
            #pragma unroll
            for (int mt = 0; mt < 2; mt++) {
                int m = wm + mt * 16 + gid;
                af[mt][0] = Ps[m * PSTR + kb + tg];
                af[mt][1] = Ps[(m + 8) * PSTR + kb + tg];
                af[mt][2] = Ps[m * PSTR + kb + tg + 4];
                af[mt][3] = Ps[(m + 8) * PSTR + kb + tg + 4];
            }
            #pragma unroll
            for (int nt = 0; nt < 2; nt++) {
                int n = wn + nt * 8 + gid;
                bf[nt][0] = Vs[(kb + tg) * VSTR + n];
                bf[nt][1] = Vs[(kb + tg + 4) * VSTR + n];
            }
            #pragma unroll
            for (int mt = 0; mt < 2; mt++)
                #pragma unroll
                for (int nt = 0; nt < 2; nt++)
                    mma_tf32(acc[mt][nt], af[mt][0], af[mt][1], af[mt][2], af[mt][3],
                             bf[nt][0], bf[nt][1]);
        }
        __syncthreads();
    }
    #pragma unroll
    for (int mt = 0; mt < 2; mt++) {
        int mA = m0 + wm + mt * 16 + gid, mB = mA + 8;
        #pragma unroll
        for (int nt = 0; nt < 2; nt++) {
            int n = wn + nt * 8 + tg * 2;
            size_t pA = (size_t)(b * Sq + mA) * Dm + h * HDm + n;
            size_t pB = (size_t)(b * Sq + mB) * Dm + h * HDm + n;
            O[pA]     = acc[mt][nt][0];
            O[pA + 1] = acc[mt][nt][1];
            O[pB]     = acc[mt][nt][2];
            O[pB + 1] = acc[mt][nt][3];
        }
    }
}

// ---------------- router: one warp per token ---------------------------------
__global__ void route_kernel(const float* __restrict__ H2,
                             const float* __restrict__ SW,
                             const float* __restrict__ SB) {
    int warp = (blockIdx.x * blockDim.x + threadIdx.x) >> 5;
    int lane = threadIdx.x & 31;
    if (warp >= TOK) return;
    const float* hrow = H2 + (size_t)warp * Dm;
    float acc[En];
    #pragma unroll
    for (int e = 0; e < En; e++) acc[e] = 0.f;
    for (int d = lane; d < Dm; d += 32) {
        float hv = hrow[d];
        const float* w = SW + d * En;
        #pragma unroll
        for (int e = 0; e < En; e++) acc[e] += hv * w[e];
    }
    #pragma unroll
    for (int e = 0; e < En; e++)
        #pragma unroll
        for (int o = 16; o; o >>= 1)
            acc[e] += __shfl_xor_sync(0xffffffffu, acc[e], o);
    if (lane == 0) {
        float best = acc[0] + SB[0];
        int be = 0;
        #pragma unroll
        for (int e = 1; e < En; e++) {
            float v = acc[e] + SB[e];
            if (v > best) { best = v; be = e; }
        }
        g_routes[warp] = be;
        atomicAdd(&g_cnt[be], 1);
    }
}

__global__ void offsets_kernel() {
    if (threadIdx.x == 0) {
        int acc = 0;
        for (int e = 0; e < En; e++) { g_off[e] = acc; acc += g_cnt[e]; }
    }
}

__global__ void scatter_kernel() {
    int t = blockIdx.x * blockDim.x + threadIdx.x;
    if (t >= TOK) return;
    int e = g_routes[t];
    int pos = atomicAdd(&g_cur[e], 1);
    g_sorted[g_off[e] + pos] = t;
}

// ---------------- launch ------------------------------------------------------
extern "C" void kernel_launch(void* const* d_in, const int* in_sizes, int n_in,
                              void* d_out, int out_size) {
    const float* x       = (const float*)d_in[0];
    // d_in[1] = indexes_list (unused by reference math)
    const float* ln1_g   = (const float*)d_in[2];
    const float* ln1_b   = (const float*)d_in[3];
    const float* qkv_w   = (const float*)d_in[4];
    const float* proj_w  = (const float*)d_in[5];
    const float* proj_b  = (const float*)d_in[6];
    const float* ln2_g   = (const float*)d_in[7];
    const float* ln2_b   = (const float*)d_in[8];
    const float* sw_w    = (const float*)d_in[9];
    const float* sw_b    = (const float*)d_in[10];
    const float* w1      = (const float*)d_in[11];
    const float* b1      = (const float*)d_in[12];
    const float* w2      = (const float*)d_in[13];
    const float* b2      = (const float*)d_in[14];
    float* out = (float*)d_out;

    float *gh, *gqkv, *gs, *go, *gh2, *gy1;
    cudaGetSymbolAddress((void**)&gh,   g_h);
    cudaGetSymbolAddress((void**)&gqkv, g_qkv);
    cudaGetSymbolAddress((void**)&gs,   g_scores);
    cudaGetSymbolAddress((void**)&go,   g_o);
    cudaGetSymbolAddress((void**)&gh2,  g_h2);
    cudaGetSymbolAddress((void**)&gy1,  g_y1);

    reset_kernel<<<1, 32>>>();

    // ln1
    ln_kernel<<<TOK, 256>>>(x, ln1_g, ln1_b, gh);
    // qkv = h @ qkv_w   [4096 x 2304]
    gemm_tf32<<<dim3(2304 / 128, TOK / 128), 256>>>(gh, qkv_w, gqkv,
                                                    TOK, 2304, Dm, nullptr, nullptr);
    // scores
    scores_tf32<<<dim3(Sq / 64, Sq / 64, BHN), 256>>>(gqkv, gs);
    // softmax
    softmax_kernel<<<BHN * Sq, 256>>>(gs);
    // o = P @ V
    av_tf32<<<dim3(Sq / 64, BHN), 256>>>(gs, gqkv, go);
    // xmid = x + o @ proj_w + proj_b   -> written into d_out
    gemm_tf32<<<dim3(Dm / 128, TOK / 128), 256>>>(go, proj_w, out,
                                                  TOK, Dm, Dm, proj_b, x);
    // ln2
    ln_kernel<<<TOK, 256>>>(out, ln2_g, ln2_b, gh2);
    // routing
    route_kernel<<<512, 256>>>(gh2, sw_w, sw_b);
    offsets_kernel<<<1, 32>>>();
    scatter_kernel<<<TOK / 256, 256>>>();
    // MoE expert GEMMs (grouped tokens); extra tiles exit early
    moe1_tf32<<<dim3(FFd / 128, TOK / 128, En), 256>>>(gh2, w1, b1, gy1);
    moe2_tf32<<<dim3(Dm / 128, TOK / 128, En), 256>>>(gy1, w2, b2, out);
}

// round 6
// speedup vs baseline: 1.3716x; 1.3716x over previous
#include <cuda_runtime.h>
#include <math.h>

#define Bsz 8
#define Sq  512
#define Dm  768
#define Hn  12
#define HDm 64
#define En  8
#define FFd 3072
#define TOK 4096
#define BHN 96

// ---------------- scratch (device globals; no allocations allowed) ----------
__device__ float g_h[TOK * Dm];
__device__ float g_qkv[TOK * 3 * Dm];
__device__ float g_o[TOK * Dm];
__device__ float g_h2[TOK * Dm];
__device__ float g_y1[(size_t)TOK * FFd];
__device__ int   g_routes[TOK];
__device__ int   g_cnt[En];
__device__ int   g_off[En];
__device__ int   g_cur[En];
__device__ int   g_sorted[TOK];

// ---------------- helpers ---------------------------------------------------
__device__ __forceinline__ float gelu_exact(float x) {
    return 0.5f * x * (1.0f + erff(x * 0.70710678118654752f));
}

__device__ __forceinline__ unsigned f2t(float f) {
    unsigned u;
    asm("cvt.rna.tf32.f32 %0, %1;" : "=r"(u) : "f"(f));
    return u;
}
// convert raw fp32 bits (loaded from smem) to tf32 with round-to-nearest
__device__ __forceinline__ unsigned t32(unsigned u) {
    return f2t(__uint_as_float(u));
}

__device__ __forceinline__ void mma_tf32(float c[4],
                                         unsigned a0, unsigned a1, unsigned a2, unsigned a3,
                                         unsigned b0, unsigned b1) {
    asm volatile(
        "mma.sync.aligned.m16n8k8.row.col.f32.tf32.tf32.f32 "
        "{%0,%1,%2,%3},{%4,%5,%6,%7},{%8,%9},{%0,%1,%2,%3};"
        : "+f"(c[0]), "+f"(c[1]), "+f"(c[2]), "+f"(c[3])
        : "r"(a0), "r"(a1), "r"(a2), "r"(a3), "r"(b0), "r"(b1));
}

__device__ __forceinline__ void cp16(unsigned* d, const void* s) {
    unsigned sd = (unsigned)__cvta_generic_to_shared(d);
    asm volatile("cp.async.cg.shared.global [%0], [%1], 16;" :: "r"(sd), "l"(s));
}
__device__ __forceinline__ void cp16z(unsigned* d, const void* s, int pred) {
    unsigned sd = (unsigned)__cvta_generic_to_shared(d);
    int sz = pred ? 16 : 0;
    asm volatile("cp.async.cg.shared.global [%0], [%1], 16, %2;" :: "r"(sd), "l"(s), "r"(sz));
}
#define CP_COMMIT() asm volatile("cp.async.commit_group;")
#define CP_WAIT0()  asm volatile("cp.async.wait_group 0;")

// ---------------- reset counters --------------------------------------------
__global__ void reset_kernel() {
    int t = threadIdx.x;
    if (t < En) { g_cnt[t] = 0; g_cur[t] = 0; }
}

// ---------------- layernorm -------------------------------------------------
__global__ void ln_kernel(const float* __restrict__ X,
                          const float* __restrict__ gam,
                          const float* __restrict__ bet,
                          float* __restrict__ Y) {
    int row = blockIdx.x;
    int tid = threadIdx.x;
    const float* x = X + (size_t)row * Dm;
    float v0 = x[tid], v1 = x[tid + 256], v2 = x[tid + 512];

    __shared__ float red[256];
    red[tid] = v0 + v1 + v2; __syncthreads();
    #pragma unroll
    for (int st = 128; st > 0; st >>= 1) {
        if (tid < st) red[tid] += red[tid + st];
        __syncthreads();
    }
    float mu = red[0] / (float)Dm;
    __syncthreads();

    float d0 = v0 - mu, d1 = v1 - mu, d2 = v2 - mu;
    red[tid] = d0 * d0 + d1 * d1 + d2 * d2; __syncthreads();
    #pragma unroll
    for (int st = 128; st > 0; st >>= 1) {
        if (tid < st) red[tid] += red[tid + st];
        __syncthreads();
    }
    float rstd = rsqrtf(red[0] / (float)Dm + 1e-5f);

    float* y = Y + (size_t)row * Dm;
    y[tid]       = d0 * rstd * gam[tid]       + bet[tid];
    y[tid + 256] = d1 * rstd * gam[tid + 256] + bet[tid + 256];
    y[tid + 512] = d2 * rstd * gam[tid + 512] + bet[tid + 512];
}

// =============================================================================
// tf32 GEMM with cp.async double buffering: C = A@B (+bias)(+resid)
// BM=128, BN=128, BK=16, 256 threads = 8 warps (2x4), warp tile 64x32.
// Fragments are cvt.rna'ed from raw fp32 at smem->reg load.
// =============================================================================
#define ASTR 20
#define BSTR 136

__global__ void gemm_tf32(const float* __restrict__ A, const float* __restrict__ B,
                          float* __restrict__ C, int M, int N, int K,
                          const float* __restrict__ bias,
                          const float* __restrict__ resid) {
    __shared__ unsigned As[2][128 * ASTR];
    __shared__ unsigned Bs[2][16 * BSTR];
    int tid = threadIdx.x;
    int warp = tid >> 5, lane = tid & 31;
    int gid = lane >> 2, tg = lane & 3;
    int wm = (warp >> 2) * 64, wn = (warp & 3) * 32;
    int m0 = blockIdx.y * 128, n0 = blockIdx.x * 128;

    float acc[4][4][4];
    #pragma unroll
    for (int i = 0; i < 4; i++)
        #pragma unroll
        for (int j = 0; j < 4; j++)
            #pragma unroll
            for (int q = 0; q < 4; q++) acc[i][j][q] = 0.f;

    int ra = tid >> 2, ca = (tid & 3) * 4;
    int rb = tid >> 5, cb = (tid & 31) * 4;

    cp16(&As[0][ra * ASTR + ca],        A + (size_t)(m0 + ra) * K + ca);
    cp16(&As[0][(ra + 64) * ASTR + ca], A + (size_t)(m0 + ra + 64) * K + ca);
    cp16(&Bs[0][rb * BSTR + cb],        B + (size_t)rb * N + n0 + cb);
    cp16(&Bs[0][(rb + 8) * BSTR + cb],  B + (size_t)(rb + 8) * N + n0 + cb);
    CP_COMMIT();

    int nk = K / 16;
    for (int kt = 0; kt < nk; kt++) {
        int s = kt & 1;
        CP_WAIT0(); __syncthreads();
        if (kt + 1 < nk) {
            int k0 = (kt + 1) * 16;
            cp16(&As[s ^ 1][ra * ASTR + ca],        A + (size_t)(m0 + ra) * K + k0 + ca);
            cp16(&As[s ^ 1][(ra + 64) * ASTR + ca], A + (size_t)(m0 + ra + 64) * K + k0 + ca);
            cp16(&Bs[s ^ 1][rb * BSTR + cb],        B + (size_t)(k0 + rb) * N + n0 + cb);
            cp16(&Bs[s ^ 1][(rb + 8) * BSTR + cb],  B + (size_t)(k0 + rb + 8) * N + n0 + cb);
            CP_COMMIT();
        }
        #pragma unroll
        for (int ks = 0; ks < 2; ks++) {
            int kb = ks * 8;
            unsigned af[4][4], bf[4][2];
            #pragma unroll
            for (int mt = 0; mt < 4; mt++) {
                int m = wm + mt * 16 + gid;
                af[mt][0] = t32(As[s][m * ASTR + kb + tg]);
                af[mt][1] = t32(As[s][(m + 8) * ASTR + kb + tg]);
                af[mt][2] = t32(As[s][m * ASTR + kb + tg + 4]);
                af[mt][3] = t32(As[s][(m + 8) * ASTR + kb + tg + 4]);
            }
            #pragma unroll
            for (int nt = 0; nt < 4; nt++) {
                int n = wn + nt * 8 + gid;
                bf[nt][0] = t32(Bs[s][(kb + tg) * BSTR + n]);
                bf[nt][1] = t32(Bs[s][(kb + tg + 4) * BSTR + n]);
            }
            #pragma unroll
            for (int mt = 0; mt < 4; mt++)
                #pragma unroll
                for (int nt = 0; nt < 4; nt++)
                    mma_tf32(acc[mt][nt], af[mt][0], af[mt][1], af[mt][2], af[mt][3],
                             bf[nt][0], bf[nt][1]);
        }
    }
    #pragma unroll
    for (int mt = 0; mt < 4; mt++) {
        int mA = m0 + wm + mt * 16 + gid, mB = mA + 8;
        #pragma unroll
        for (int nt = 0; nt < 4; nt++) {
            int n = n0 + wn + nt * 8 + tg * 2;
            float v0 = acc[mt][nt][0], v1 = acc[mt][nt][1];
            float v2 = acc[mt][nt][2], v3 = acc[mt][nt][3];
            if (bias) {
                float b0 = bias[n], b1 = bias[n + 1];
                v0 += b0; v1 += b1; v2 += b0; v3 += b1;
            }
            if (resid) {
                v0 += resid[(size_t)mA * N + n];
                v1 += resid[(size_t)mA * N + n + 1];
                v2 += resid[(size_t)mB * N + n];
                v3 += resid[(size_t)mB * N + n + 1];
            }
            C[(size_t)mA * N + n]     = v0;
            C[(size_t)mA * N + n + 1] = v1;
            C[(size_t)mB * N + n]     = v2;
            C[(size_t)mB * N + n + 1] = v3;
        }
    }
}

// ---------------- MoE GEMM1: Y1 = gelu(gather(H2) @ W1[e] + b1[e]) ----------
__global__ void moe1_tf32(const float* __restrict__ H2,
                          const float* __restrict__ W1,
                          const float* __restrict__ B1,
                          float* __restrict__ Y1) {
    int e = blockIdx.z;
    int cnt = g_cnt[e];
    int m0 = blockIdx.y * 128;
    if (m0 >= cnt) return;
    int off = g_off[e];
    const float* B = W1 + (size_t)e * Dm * FFd;
    const int N = FFd, K = Dm;
    int n0 = blockIdx.x * 128;

    __shared__ unsigned As[2][128 * ASTR];
    __shared__ unsigned Bs[2][16 * BSTR];
    __shared__ int toks[128];
    int tid = threadIdx.x;
    int warp = tid >> 5, lane = tid & 31;
    int gid = lane >> 2, tg = lane & 3;
    int wm = (warp >> 2) * 64, wn = (warp & 3) * 32;
    if (tid < 128) {
        int m = m0 + tid;
        toks[tid] = (m < cnt) ? g_sorted[off + m] : -1;
    }
    __syncthreads();

    float acc[4][4][4];
    #pragma unroll
    for (int i = 0; i < 4; i++)
        #pragma unroll
        for (int j = 0; j < 4; j++)
            #pragma unroll
            for (int q = 0; q < 4; q++) acc[i][j][q] = 0.f;

    int ra = tid >> 2, ca = (tid & 3) * 4;
    int rb = tid >> 5, cb = (tid & 31) * 4;
    int t0 = toks[ra], t1 = toks[ra + 64];
    const float* srcA0 = H2 + (size_t)(t0 >= 0 ? t0 : 0) * Dm + ca;
    const float* srcA1 = H2 + (size_t)(t1 >= 0 ? t1 : 0) * Dm + ca;

    cp16z(&As[0][ra * ASTR + ca],        srcA0, t0 >= 0);
    cp16z(&As[0][(ra + 64) * ASTR + ca], srcA1, t1 >= 0);
    cp16(&Bs[0][rb * BSTR + cb],        B + (size_t)rb * N + n0 + cb);
    cp16(&Bs[0][(rb + 8) * BSTR + cb],  B + (size_t)(rb + 8) * N + n0 + cb);
    CP_COMMIT();

    int nk = K / 16;
    for (int kt = 0; kt < nk; kt++) {
        int s = kt & 1;
        CP_WAIT0(); __syncthreads();
        if (kt + 1 < nk) {
            int k0 = (kt + 1) * 16;
            cp16z(&As[s ^ 1][ra * ASTR + ca],        srcA0 + k0, t0 >= 0);
            cp16z(&As[s ^ 1][(ra + 64) * ASTR + ca], srcA1 + k0, t1 >= 0);
            cp16(&Bs[s ^ 1][rb * BSTR + cb],        B + (size_t)(k0 + rb) * N + n0 + cb);
            cp16(&Bs[s ^ 1][(rb + 8) * BSTR + cb],  B + (size_t)(k0 + rb + 8) * N + n0 + cb);
            CP_COMMIT();
        }
        #pragma unroll
        for (int ks = 0; ks < 2; ks++) {
            int kb = ks * 8;
            unsigned af[4][4], bf[4][2];
            #pragma unroll
            for (int mt = 0; mt < 4; mt++) {
                int m = wm + mt * 16 + gid;
                af[mt][0] = t32(As[s][m * ASTR + kb + tg]);
                af[mt][1] = t32(As[s][(m + 8) * ASTR + kb + tg]);
                af[mt][2] = t32(As[s][m * ASTR + kb + tg + 4]);
                af[mt][3] = t32(As[s][(m + 8) * ASTR + kb + tg + 4]);
            }
            #pragma unroll
            for (int nt = 0; nt < 4; nt++) {
                int n = wn + nt * 8 + gid;
                bf[nt][0] = t32(Bs[s][(kb + tg) * BSTR + n]);
                bf[nt][1] = t32(Bs[s][(kb + tg + 4) * BSTR + n]);
            }
            #pragma unroll
            for (int mt = 0; mt < 4; mt++)
                #pragma unroll
                for (int nt = 0; nt < 4; nt++)
                    mma_tf32(acc[mt][nt], af[mt][0], af[mt][1], af[mt][2], af[mt][3],
                             bf[nt][0], bf[nt][1]);
        }
    }
    #pragma unroll
    for (int mt = 0; mt < 4; mt++) {
        int lmA = wm + mt * 16 + gid;
        int gmA = m0 + lmA, gmB = gmA + 8;
        #pragma unroll
        for (int nt = 0; nt < 4; nt++) {
            int n = wn + nt * 8 + tg * 2;
            float b0 = B1[e * FFd + n0 + n], b1 = B1[e * FFd + n0 + n + 1];
            if (gmA < cnt) {
                Y1[(size_t)(off + gmA) * FFd + n0 + n]     = gelu_exact(acc[mt][nt][0] + b0);
                Y1[(size_t)(off + gmA) * FFd + n0 + n + 1] = gelu_exact(acc[mt][nt][1] + b1);
            }
            if (gmB < cnt) {
                Y1[(size_t)(off + gmB) * FFd + n0 + n]     = gelu_exact(acc[mt][nt][2] + b0);
                Y1[(size_t)(off + gmB) * FFd + n0 + n + 1] = gelu_exact(acc[mt][nt][3] + b1);
            }
        }
    }
}

// ---------------- MoE GEMM2: out[t] += gelu(Y1 @ W2[e] + b2[e]) -------------
__global__ void moe2_tf32(const float* __restrict__ Y1,
                          const float* __restrict__ W2,
                          const float* __restrict__ B2,
                          float* __restrict__ OUT) {
    int e = blockIdx.z;
    int cnt = g_cnt[e];
    int m0 = blockIdx.y * 128;
    if (m0 >= cnt) return;
    int off = g_off[e];
    const float* B = W2 + (size_t)e * FFd * Dm;
    const int N = Dm, K = FFd;
    int n0 = blockIdx.x * 128;

    __shared__ unsigned As[2][128 * ASTR];
    __shared__ unsigned Bs[2][16 * BSTR];
    __shared__ int toks[128];
    int tid = threadIdx.x;
    int warp = tid >> 5, lane = tid & 31;
    int gid = lane >> 2, tg = lane & 3;
    int wm = (warp >> 2) * 64, wn = (warp & 3) * 32;
    if (tid < 128) {
        int m = m0 + tid;
        toks[tid] = (m < cnt) ? g_sorted[off + m] : -1;
    }
    __syncthreads();

    float acc[4][4][4];
    #pragma unroll
    for (int i = 0; i < 4; i++)
        #pragma unroll
        for (int j = 0; j < 4; j++)
            #pragma unroll
            for (int q = 0; q < 4; q++) acc[i][j][q] = 0.f;

    int ra = tid >> 2, ca = (tid & 3) * 4;
    int rb = tid >> 5, cb = (tid & 31) * 4;
    int okA0 = (m0 + ra) < cnt, okA1 = (m0 + ra + 64) < cnt;
    const float* srcA0 = Y1 + (size_t)(off + (okA0 ? m0 + ra : 0)) * FFd + ca;
    const float* srcA1 = Y1 + (size_t)(off + (okA1 ? m0 + ra + 64 : 0)) * FFd + ca;

    cp16z(&As[0][ra * ASTR + ca],        srcA0, okA0);
    cp16z(&As[0][(ra + 64) * ASTR + ca], srcA1, okA1);
    cp16(&Bs[0][rb * BSTR + cb],        B + (size_t)rb * N + n0 + cb);
    cp16(&Bs[0][(rb + 8) * BSTR + cb],  B + (size_t)(rb + 8) * N + n0 + cb);
    CP_COMMIT();

    int nk = K / 16;
    for (int kt = 0; kt < nk; kt++) {
        int s = kt & 1;
        CP_WAIT0(); __syncthreads();
        if (kt + 1 < nk) {
            int k0 = (kt + 1) * 16;
            cp16z(&As[s ^ 1][ra * ASTR + ca],        srcA0 + k0, okA0);
            cp16z(&As[s ^ 1][(ra + 64) * ASTR + ca], srcA1 + k0, okA1);
            cp16(&Bs[s ^ 1][rb * BSTR + cb],        B + (size_t)(k0 + rb) * N + n0 + cb);
            cp16(&Bs[s ^ 1][(rb + 8) * BSTR + cb],  B + (size_t)(k0 + rb + 8) * N + n0 + cb);
            CP_COMMIT();
        }
        #pragma unroll
        for (int ks = 0; ks < 2; ks++) {
            int kb = ks * 8;
            unsigned af[4][4], bf[4][2];
            #pragma unroll
            for (int mt = 0; mt < 4; mt++) {
                int m = wm + mt * 16 + gid;
                af[mt][0] = t32(As[s][m * ASTR + kb + tg]);
                af[mt][1] = t32(As[s][(m + 8) * ASTR + kb + tg]);
                af[mt][2] = t32(As[s][m * ASTR + kb + tg + 4]);
                af[mt][3] = t32(As[s][(m + 8) * ASTR + kb + tg + 4]);
            }
            #pragma unroll
            for (int nt = 0; nt < 4; nt++) {
                int n = wn + nt * 8 + gid;
                bf[nt][0] = t32(Bs[s][(kb + tg) * BSTR + n]);
                bf[nt][1] = t32(Bs[s][(kb + tg + 4) * BSTR + n]);
            }
            #pragma unroll
            for (int mt = 0; mt < 4; mt++)
                #pragma unroll
                for (int nt = 0; nt < 4; nt++)
                    mma_tf32(acc[mt][nt], af[mt][0], af[mt][1], af[mt][2], af[mt][3],
                             bf[nt][0], bf[nt][1]);
        }
    }
    #pragma unroll
    for (int mt = 0; mt < 4; mt++) {
        int lmA = wm + mt * 16 + gid;
        int gmA = m0 + lmA, gmB = gmA + 8;
        int tA = toks[lmA], tB = toks[lmA + 8];
        #pragma unroll
        for (int nt = 0; nt < 4; nt++) {
            int n = wn + nt * 8 + tg * 2;
            float b0 = B2[e * Dm + n0 + n], b1 = B2[e * Dm + n0 + n + 1];
            if (gmA < cnt) {
                OUT[(size_t)tA * Dm + n0 + n]     += gelu_exact(acc[mt][nt][0] + b0);
                OUT[(size_t)tA * Dm + n0 + n + 1] += gelu_exact(acc[mt][nt][1] + b1);
            }
            if (gmB < cnt) {
                OUT[(size_t)tB * Dm + n0 + n]     += gelu_exact(acc[mt][nt][2] + b0);
                OUT[(size_t)tB * Dm + n0 + n + 1] += gelu_exact(acc[mt][nt][3] + b1);
            }
        }
    }
}

// =============================================================================
// Fused flash attention: per block = one (b,h) x 64 query rows, full 512 keys.
// 128 threads = 4 warps, each warp owns 16 query rows. Online softmax.
// =============================================================================
#define QSTR 68
#define VSTR 72
#define FA_SMEM ((64 * QSTR + 64 * QSTR + 64 * VSTR) * 4)

__global__ void flash_tf32(const float* __restrict__ QKV, float* __restrict__ O) {
    extern __shared__ unsigned sm[];
    unsigned* Qs = sm;                       // 64 x QSTR (later reused as P)
    unsigned* Ks = sm + 64 * QSTR;           // 64 x QSTR
    unsigned* Vs = sm + 128 * QSTR;          // 64 x VSTR

    int bh = blockIdx.y;
    int b = bh / Hn, h = bh % Hn;
    int m0 = blockIdx.x * 64;
    int tid = threadIdx.x;
    int warp = tid >> 5, lane = tid & 31;
    int gid = lane >> 2, tg = lane & 3;
    int wm = warp * 16;

    // --- load Q tile (64 x 64) ---
    #pragma unroll
    for (int l = 0; l < 8; l++) {
        int idx = tid + l * 128, r = idx >> 4, c4 = (idx & 15) * 4;
        cp16(&Qs[r * QSTR + c4],
             QKV + (size_t)(b * Sq + m0 + r) * 2304 + h * HDm + c4);
    }
    CP_COMMIT(); CP_WAIT0(); __syncthreads();

    // Q fragments to registers (cvt.rna once here)
    unsigned aq[8][4];
    #pragma unroll
    for (int k8 = 0; k8 < 8; k8++) {
        int kb = k8 * 8;
        aq[k8][0] = t32(Qs[(wm + gid) * QSTR + kb + tg]);
        aq[k8][1] = t32(Qs[(wm + gid + 8) * QSTR + kb + tg]);
        aq[k8][2] = t32(Qs[(wm + gid) * QSTR + kb + tg + 4]);
        aq[k8][3] = t32(Qs[(wm + gid + 8) * QSTR + kb + tg + 4]);
    }
    __syncthreads();  // Qs free -> reuse as P staging

    float mr0 = -1e30f, mr1 = -1e30f, lr0 = 0.f, lr1 = 0.f;
    float o[8][4];
    #pragma unroll
    for (int nt = 0; nt < 8; nt++)
        #pragma unroll
        for (int q = 0; q < 4; q++) o[nt][q] = 0.f;

    for (int n0 = 0; n0 < Sq; n0 += 64) {
        // --- load K and V chunk (64 x 64 each) ---
        #pragma unroll
        for (int l = 0; l < 8; l++) {
            int idx = tid + l * 128, r = idx >> 4, c4 = (idx & 15) * 4;
            cp16(&Ks[r * QSTR + c4],
                 QKV + (size_t)(b * Sq + n0 + r) * 2304 + Dm + h * HDm + c4);
        }
        #pragma unroll
        for (int l = 0; l < 8; l++) {
            int idx = tid + l * 128, r = idx >> 4, c4 = (idx & 15) * 4;
            cp16(&Vs[r * VSTR + c4],
                 QKV + (size_t)(b * Sq + n0 + r) * 2304 + 2 * Dm + h * HDm + c4);
        }
        CP_COMMIT(); CP_WAIT0(); __syncthreads();

        // --- S = Q @ K^T for this warp's 16 rows x 64 keys ---
        float s[8][4];
        #pragma unroll
        for (int nt = 0; nt < 8; nt++)
            #pragma unroll
            for (int q = 0; q < 4; q++) s[nt][q] = 0.f;
        #pragma unroll
        for (int k8 = 0; k8 < 8; k8++) {
            int kb = k8 * 8;
            #pragma unroll
            for (int nt = 0; nt < 8; nt++) {
                int n = nt * 8 + gid;
                unsigned b0 = t32(Ks[n * QSTR + kb + tg]);
                unsigned b1 = t32(Ks[n * QSTR + kb + tg + 4]);
                mma_tf32(s[nt], aq[k8][0], aq[k8][1], aq[k8][2], aq[k8][3], b0, b1);
            }
        }

        // --- online softmax ---
        const float sc = 0.125f;
        float mx0 = -1e30f, mx1 = -1e30f;
        #pragma unroll
        for (int nt = 0; nt < 8; nt++) {
            s[nt][0] *= sc; s[nt][1] *= sc; s[nt][2] *= sc; s[nt][3] *= sc;
            mx0 = fmaxf(mx0, fmaxf(s[nt][0], s[nt][1]));
            mx1 = fmaxf(mx1, fmaxf(s[nt][2], s[nt][3]));
        }
        mx0 = fmaxf(mx0, __shfl_xor_sync(0xffffffffu, mx0, 1));
        mx0 = fmaxf(mx0, __shfl_xor_sync(0xffffffffu, mx0, 2));
        mx1 = fmaxf(mx1, __shfl_xor_sync(0xffffffffu, mx1, 1));
        mx1 = fmaxf(mx1, __shfl_xor_sync(0xffffffffu, mx1, 2));
        float mn0 = fmaxf(mr0, mx0), mn1 = fmaxf(mr1, mx1);
        float a0 = __expf(mr0 - mn0), a1 = __expf(mr1 - mn1);
        float sum0 = 0.f, sum1 = 0.f;
        #pragma unroll
        for (int nt = 0; nt < 8; nt++) {
            s[nt][0] = __expf(s[nt][0] - mn0);
            s[nt][1] = __expf(s[nt][1] - mn0);
            s[nt][2] = __expf(s[nt][2] - mn1);
            s[nt][3] = __expf(s[nt][3] - mn1);
            sum0 += s[nt][0] + s[nt][1];
            sum1 += s[nt][2] + s[nt][3];
        }
        sum0 += __shfl_xor_sync(0xffffffffu, sum0, 1);
        sum0 += __shfl_xor_sync(0xffffffffu, sum0, 2);
        sum1 += __shfl_xor_sync(0xffffffffu, sum1, 1);
        sum1 += __shfl_xor_sync(0xffffffffu, sum1, 2);
        lr0 = lr0 * a0 + sum0;
        lr1 = lr1 * a1 + sum1;
        mr0 = mn0; mr1 = mn1;
        #pragma unroll
        for (int nt = 0; nt < 8; nt++) {
            o[nt][0] *= a0; o[nt][1] *= a0;
            o[nt][2] *= a1; o[nt][3] *= a1;
        }

        // --- stage P into smem as tf32 (warp-local rows) ---
        unsigned* Ps = Qs;
        #pragma unroll
        for (int nt = 0; nt < 8; nt++) {
            int c = nt * 8 + tg * 2;
            Ps[(wm + gid) * QSTR + c]         = f2t(s[nt][0]);
            Ps[(wm + gid) * QSTR + c + 1]     = f2t(s[nt][1]);
            Ps[(wm + gid + 8) * QSTR + c]     = f2t(s[nt][2]);
            Ps[(wm + gid + 8) * QSTR + c + 1] = f2t(s[nt][3]);
        }
        __syncwarp();

        // --- O += P @ V ---
        #pragma unroll
        for (int kb = 0; kb < 64; kb += 8) {
            unsigned p0 = Ps[(wm + gid) * QSTR + kb + tg];
            unsigned p1 = Ps[(wm + gid + 8) * QSTR + kb + tg];
            unsigned p2 = Ps[(wm + gid) * QSTR + kb + tg + 4];
            unsigned p3 = Ps[(wm + gid + 8) * QSTR + kb + tg + 4];
            #pragma unroll
            for (int nt = 0; nt < 8; nt++) {
                int n = nt * 8 + gid;
                unsigned v0 = t32(Vs[(kb + tg) * VSTR + n]);
                unsigned v1 = t32(Vs[(kb + tg + 4) * VSTR + n]);
                mma_tf32(o[nt], p0, p1, p2, p3, v0, v1);
            }
        }
        __syncthreads();  // before next chunk overwrites Ks/Vs
    }

    // --- epilogue: O /= l, write out ---
    float inv0 = 1.0f / lr0, inv1 = 1.0f / lr1;
    int rA = b * Sq + m0 + wm + gid, rB = rA + 8;
    #pragma unroll
    for (int nt = 0; nt < 8; nt++) {
        int c = h * HDm + nt * 8 + tg * 2;
        O[(size_t)rA * Dm + c]     = o[nt][0] * inv0;
        O[(size_t)rA * Dm + c + 1] = o[nt][1] * inv0;
        O[(size_t)rB * Dm + c]     = o[nt][2] * inv1;
        O[(size_t)rB * Dm + c + 1] = o[nt][3] * inv1;
    }
}

// ---------------- router: one warp per token ---------------------------------
__global__ void route_kernel(const float* __restrict__ H2,
                             const float* __restrict__ SW,
                             const float* __restrict__ SB) {
    int warp = (blockIdx.x * blockDim.x + threadIdx.x) >> 5;
    int lane = threadIdx.x & 31;
    if (warp >= TOK) return;
    const float* hrow = H2 + (size_t)warp * Dm;
    float acc[En];
    #pragma unroll
    for (int e = 0; e < En; e++) acc[e] = 0.f;
    for (int d = lane; d < Dm; d += 32) {
        float hv = hrow[d];
        const float* w = SW + d * En;
        #pragma unroll
        for (int e = 0; e < En; e++) acc[e] += hv * w[e];
    }
    #pragma unroll
    for (int e = 0; e < En; e++)
        #pragma unroll
        for (int o = 16; o; o >>= 1)
            acc[e] += __shfl_xor_sync(0xffffffffu, acc[e], o);
    if (lane == 0) {
        float best = acc[0] + SB[0];
        int be = 0;
        #pragma unroll
        for (int e = 1; e < En; e++) {
            float v = acc[e] + SB[e];
            if (v > best) { best = v; be = e; }
        }
        g_routes[warp] = be;
        atomicAdd(&g_cnt[be], 1);
    }
}

__global__ void offsets_kernel() {
    if (threadIdx.x == 0) {
        int acc = 0;
        for (int e = 0; e < En; e++) { g_off[e] = acc; acc += g_cnt[e]; }
    }
}

__global__ void scatter_kernel() {
    int t = blockIdx.x * blockDim.x + threadIdx.x;
    if (t >= TOK) return;
    int e = g_routes[t];
    int pos = atomicAdd(&g_cur[e], 1);
    g_sorted[g_off[e] + pos] = t;
}

// ---------------- launch ------------------------------------------------------
extern "C" void kernel_launch(void* const* d_in, const int* in_sizes, int n_in,
                              void* d_out, int out_size) {
    const float* x       = (const float*)d_in[0];
    // d_in[1] = indexes_list (unused by reference math)
    const float* ln1_g   = (const float*)d_in[2];
    const float* ln1_b   = (const float*)d_in[3];
    const float* qkv_w   = (const float*)d_in[4];
    const float* proj_w  = (const float*)d_in[5];
    const float* proj_b  = (const float*)d_in[6];
    const float* ln2_g   = (const float*)d_in[7];
    const float* ln2_b   = (const float*)d_in[8];
    const float* sw_w    = (const float*)d_in[9];
    const float* sw_b    = (const float*)d_in[10];
    const float* w1      = (const float*)d_in[11];
    const float* b1      = (const float*)d_in[12];
    const float* w2      = (const float*)d_in[13];
    const float* b2      = (const float*)d_in[14];
    float* out = (float*)d_out;

    float *gh, *gqkv, *go, *gh2, *gy1;
    cudaGetSymbolAddress((void**)&gh,   g_h);
    cudaGetSymbolAddress((void**)&gqkv, g_qkv);
    cudaGetSymbolAddress((void**)&go,   g_o);
    cudaGetSymbolAddress((void**)&gh2,  g_h2);
    cudaGetSymbolAddress((void**)&gy1,  g_y1);

    static int smem_set = 0;
    if (!smem_set) {
        cudaFuncSetAttribute(flash_tf32, cudaFuncAttributeMaxDynamicSharedMemorySize, FA_SMEM);
        smem_set = 1;
    }

    reset_kernel<<<1, 32>>>();

    // ln1
    ln_kernel<<<TOK, 256>>>(x, ln1_g, ln1_b, gh);
    // qkv = h @ qkv_w   [4096 x 2304]
    gemm_tf32<<<dim3(2304 / 128, TOK / 128), 256>>>(gh, qkv_w, gqkv,
                                                    TOK, 2304, Dm, nullptr, nullptr);
    // fused attention (scores + softmax + PV)
    flash_tf32<<<dim3(Sq / 64, BHN), 128, FA_SMEM>>>(gqkv, go);
    // xmid = x + o @ proj_w + proj_b   -> written into d_out
    gemm_tf32<<<dim3(Dm / 128, TOK / 128), 256>>>(go, proj_w, out,
                                                  TOK, Dm, Dm, proj_b, x);
    // ln2
    ln_kernel<<<TOK, 256>>>(out, ln2_g, ln2_b, gh2);
    // routing
    route_kernel<<<512, 256>>>(gh2, sw_w, sw_b);
    offsets_kernel<<<1, 32>>>();
    scatter_kernel<<<TOK / 256, 256>>>();
    // MoE expert GEMMs (grouped tokens); extra tiles exit early
    moe1_tf32<<<dim3(FFd / 128, TOK / 128, En), 256>>>(gh2, w1, b1, gy1);
    moe2_tf32<<<dim3(Dm / 128, TOK / 128, En), 256>>>(gy1, w2, b2, out);
}

// round 7
// speedup vs baseline: 1.4420x; 1.0513x over previous
#include <cuda_runtime.h>
#include <math.h>

#define Bsz 8
#define Sq  512
#define Dm  768
#define Hn  12
#define HDm 64
#define En  8
#define FFd 3072
#define TOK 4096
#define BHN 96

// ---------------- scratch (device globals; no allocations allowed) ----------
__device__ float g_h[TOK * Dm];
__device__ float g_qkv[TOK * 3 * Dm];
__device__ float g_o[TOK * Dm];
__device__ float g_h2[TOK * Dm];
__device__ float g_y1[(size_t)TOK * FFd];
__device__ int   g_routes[TOK];
__device__ int   g_cnt[En];
__device__ int   g_off[En];
__device__ int   g_cur[En];
__device__ int   g_sorted[TOK];

// ---------------- helpers ---------------------------------------------------
__device__ __forceinline__ float gelu_exact(float x) {
    return 0.5f * x * (1.0f + erff(x * 0.70710678118654752f));
}

__device__ __forceinline__ unsigned f2t(float f) {
    unsigned u;
    asm("cvt.rna.tf32.f32 %0, %1;" : "=r"(u) : "f"(f));
    return u;
}
__device__ __forceinline__ unsigned t32(unsigned u) {
    return f2t(__uint_as_float(u));
}

__device__ __forceinline__ void mma_tf32(float c[4],
                                         unsigned a0, unsigned a1, unsigned a2, unsigned a3,
                                         unsigned b0, unsigned b1) {
    asm volatile(
        "mma.sync.aligned.m16n8k8.row.col.f32.tf32.tf32.f32 "
        "{%0,%1,%2,%3},{%4,%5,%6,%7},{%8,%9},{%0,%1,%2,%3};"
        : "+f"(c[0]), "+f"(c[1]), "+f"(c[2]), "+f"(c[3])
        : "r"(a0), "r"(a1), "r"(a2), "r"(a3), "r"(b0), "r"(b1));
}

__device__ __forceinline__ void cp16(unsigned* d, const void* s) {
    unsigned sd = (unsigned)__cvta_generic_to_shared(d);
    asm volatile("cp.async.cg.shared.global [%0], [%1], 16;" :: "r"(sd), "l"(s));
}
__device__ __forceinline__ void cp16z(unsigned* d, const void* s, int pred) {
    unsigned sd = (unsigned)__cvta_generic_to_shared(d);
    int sz = pred ? 16 : 0;
    asm volatile("cp.async.cg.shared.global [%0], [%1], 16, %2;" :: "r"(sd), "l"(s), "r"(sz));
}
#define CP_COMMIT() asm volatile("cp.async.commit_group;")
#define CP_WAIT0()  asm volatile("cp.async.wait_group 0;")
#define CP_WAIT1()  asm volatile("cp.async.wait_group 1;")

// ---------------- reset counters --------------------------------------------
__global__ void reset_kernel() {
    int t = threadIdx.x;
    if (t < En) { g_cnt[t] = 0; g_cur[t] = 0; }
}

// ---------------- layernorm -------------------------------------------------
__global__ void ln_kernel(const float* __restrict__ X,
                          const float* __restrict__ gam,
                          const float* __restrict__ bet,
                          float* __restrict__ Y) {
    int row = blockIdx.x;
    int tid = threadIdx.x;
    const float* x = X + (size_t)row * Dm;
    float v0 = x[tid], v1 = x[tid + 256], v2 = x[tid + 512];

    __shared__ float red[256];
    red[tid] = v0 + v1 + v2; __syncthreads();
    #pragma unroll
    for (int st = 128; st > 0; st >>= 1) {
        if (tid < st) red[tid] += red[tid + st];
        __syncthreads();
    }
    float mu = red[0] / (float)Dm;
    __syncthreads();

    float d0 = v0 - mu, d1 = v1 - mu, d2 = v2 - mu;
    red[tid] = d0 * d0 + d1 * d1 + d2 * d2; __syncthreads();
    #pragma unroll
    for (int st = 128; st > 0; st >>= 1) {
        if (tid < st) red[tid] += red[tid + st];
        __syncthreads();
    }
    float rstd = rsqrtf(red[0] / (float)Dm + 1e-5f);

    float* y = Y + (size_t)row * Dm;
    y[tid]       = d0 * rstd * gam[tid]       + bet[tid];
    y[tid + 256] = d1 * rstd * gam[tid + 256] + bet[tid + 256];
    y[tid + 512] = d2 * rstd * gam[tid + 512] + bet[tid + 512];
}

// =============================================================================
// tf32 GEMM: BM=128, BN=128, BK=32, 3-stage cp.async ring, 256 thr = 8 warps.
// Warp tile 64x32. Dynamic smem. Fragments cvt.rna'ed at smem->reg load.
// =============================================================================
#define BKt  32
#define ASTR 36
#define BSTR 136
#define A_SZ (128 * ASTR)
#define B_SZ (BKt * BSTR)
#define NSTG 3
#define GEMM_SMEM (NSTG * (A_SZ + B_SZ) * 4)

// frag-compute for one 32-deep stage
#define GEMM_STAGE_MMA(Asb, Bsb)                                               \
    _Pragma("unroll")                                                          \
    for (int ks = 0; ks < 4; ks++) {                                           \
        int kb = ks * 8;                                                       \
        unsigned af[4][4], bf[4][2];                                           \
        _Pragma("unroll")                                                      \
        for (int mt = 0; mt < 4; mt++) {                                       \
            int m = wm + mt * 16 + gid;                                        \
            af[mt][0] = t32((Asb)[m * ASTR + kb + tg]);                        \
            af[mt][1] = t32((Asb)[(m + 8) * ASTR + kb + tg]);                  \
            af[mt][2] = t32((Asb)[m * ASTR + kb + tg + 4]);                    \
            af[mt][3] = t32((Asb)[(m + 8) * ASTR + kb + tg + 4]);              \
        }                                                                      \
        _Pragma("unroll")                                                      \
        for (int nt = 0; nt < 4; nt++) {                                       \
            int n = wn + nt * 8 + gid;                                         \
            bf[nt][0] = t32((Bsb)[(kb + tg) * BSTR + n]);                      \
            bf[nt][1] = t32((Bsb)[(kb + tg + 4) * BSTR + n]);                  \
        }                                                                      \
        _Pragma("unroll")                                                      \
        for (int mt = 0; mt < 4; mt++)                                         \
            _Pragma("unroll")                                                  \
            for (int nt = 0; nt < 4; nt++)                                     \
                mma_tf32(acc[mt][nt], af[mt][0], af[mt][1], af[mt][2],         \
                         af[mt][3], bf[nt][0], bf[nt][1]);                     \
    }

__global__ void gemm_tf32(const float* __restrict__ A, const float* __restrict__ B,
                          float* __restrict__ C, int M, int N, int K,
                          const float* __restrict__ bias,
                          const float* __restrict__ resid) {
    extern __shared__ unsigned smg[];
    unsigned* As = smg;
    unsigned* Bs = smg + NSTG * A_SZ;

    int tid = threadIdx.x;
    int warp = tid >> 5, lane = tid & 31;
    int gid = lane >> 2, tg = lane & 3;
    int wm = (warp >> 2) * 64, wn = (warp & 3) * 32;
    int m0 = blockIdx.y * 128, n0 = blockIdx.x * 128;

    float acc[4][4][4];
    #pragma unroll
    for (int i = 0; i < 4; i++)
        #pragma unroll
        for (int j = 0; j < 4; j++)
            #pragma unroll
            for (int q = 0; q < 4; q++) acc[i][j][q] = 0.f;

    int raA = tid >> 3, caA = (tid & 7) * 4;    // A: 4 rows/thread (stride 32)
    int raB = tid >> 5, caB = (tid & 31) * 4;   // B: 4 rows/thread (stride 8)

    #define G_LOAD(st, gk)                                                         \
        _Pragma("unroll")                                                          \
        for (int l = 0; l < 4; l++) {                                              \
            int r = raA + l * 32;                                                  \
            cp16(&As[(st) * A_SZ + r * ASTR + caA],                                \
                 A + (size_t)(m0 + r) * K + (gk) + caA);                           \
        }                                                                          \
        _Pragma("unroll")                                                          \
        for (int l = 0; l < 4; l++) {                                              \
            int r = raB + l * 8;                                                   \
            cp16(&Bs[(st) * B_SZ + r * BSTR + caB],                                \
                 B + (size_t)((gk) + r) * N + n0 + caB);                           \
        }                                                                          \
        CP_COMMIT();

    G_LOAD(0, 0)
    G_LOAD(1, BKt)

    int nk = K / BKt;
    for (int kt = 0; kt < nk; kt++) {
        int s = kt % NSTG;
        CP_WAIT1(); __syncthreads();
        if (kt + 2 < nk) {
            int st = (kt + 2) % NSTG;
            G_LOAD(st, (kt + 2) * BKt)
        } else {
            CP_COMMIT();
        }
        GEMM_STAGE_MMA(&As[s * A_SZ], &Bs[s * B_SZ])
    }
    #undef G_LOAD

    #pragma unroll
    for (int mt = 0; mt < 4; mt++) {
        int mA = m0 + wm + mt * 16 + gid, mB = mA + 8;
        #pragma unroll
        for (int nt = 0; nt < 4; nt++) {
            int n = n0 + wn + nt * 8 + tg * 2;
            float v0 = acc[mt][nt][0], v1 = acc[mt][nt][1];
            float v2 = acc[mt][nt][2], v3 = acc[mt][nt][3];
            if (bias) {
                float b0 = bias[n], b1 = bias[n + 1];
                v0 += b0; v1 += b1; v2 += b0; v3 += b1;
            }
            if (resid) {
                v0 += resid[(size_t)mA * N + n];
                v1 += resid[(size_t)mA * N + n + 1];
                v2 += resid[(size_t)mB * N + n];
                v3 += resid[(size_t)mB * N + n + 1];
            }
            C[(size_t)mA * N + n]     = v0;
            C[(size_t)mA * N + n + 1] = v1;
            C[(size_t)mB * N + n]     = v2;
            C[(size_t)mB * N + n + 1] = v3;
        }
    }
}

// ---------------- MoE GEMM1: Y1 = gelu(gather(H2) @ W1[e] + b1[e]) ----------
__global__ void moe1_tf32(const float* __restrict__ H2,
                          const float* __restrict__ W1,
                          const float* __restrict__ B1,
                          float* __restrict__ Y1) {
    int e = blockIdx.z;
    int cnt = g_cnt[e];
    int m0 = blockIdx.y * 128;
    if (m0 >= cnt) return;
    int off = g_off[e];
    const float* B = W1 + (size_t)e * Dm * FFd;
    const int N = FFd, K = Dm;
    int n0 = blockIdx.x * 128;

    extern __shared__ unsigned smg[];
    unsigned* As = smg;
    unsigned* Bs = smg + NSTG * A_SZ;
    __shared__ int toks[128];

    int tid = threadIdx.x;
    int warp = tid >> 5, lane = tid & 31;
    int gid = lane >> 2, tg = lane & 3;
    int wm = (warp >> 2) * 64, wn = (warp & 3) * 32;
    if (tid < 128) {
        int m = m0 + tid;
        toks[tid] = (m < cnt) ? g_sorted[off + m] : -1;
    }
    __syncthreads();

    float acc[4][4][4];
    #pragma unroll
    for (int i = 0; i < 4; i++)
        #pragma unroll
        for (int j = 0; j < 4; j++)
            #pragma unroll
            for (int q = 0; q < 4; q++) acc[i][j][q] = 0.f;

    int raA = tid >> 3, caA = (tid & 7) * 4;
    int raB = tid >> 5, caB = (tid & 31) * 4;
    int tk[4];
    #pragma unroll
    for (int l = 0; l < 4; l++) tk[l] = toks[raA + l * 32];

    #define M1_LOAD(st, gk)                                                        \
        _Pragma("unroll")                                                          \
        for (int l = 0; l < 4; l++) {                                              \
            int r = raA + l * 32;                                                  \
            cp16z(&As[(st) * A_SZ + r * ASTR + caA],                               \
                  H2 + (size_t)(tk[l] >= 0 ? tk[l] : 0) * Dm + (gk) + caA,         \
                  tk[l] >= 0);                                                     \
        }                                                                          \
        _Pragma("unroll")                                                          \
        for (int l = 0; l < 4; l++) {                                              \
            int r = raB + l * 8;                                                   \
            cp16(&Bs[(st) * B_SZ + r * BSTR + caB],                                \
                 B + (size_t)((gk) + r) * N + n0 + caB);                           \
        }                                                                          \
        CP_COMMIT();

    M1_LOAD(0, 0)
    M1_LOAD(1, BKt)

    int nk = K / BKt;
    for (int kt = 0; kt < nk; kt++) {
        int s = kt % NSTG;
        CP_WAIT1(); __syncthreads();
        if (kt + 2 < nk) {
            int st = (kt + 2) % NSTG;
            M1_LOAD(st, (kt + 2) * BKt)
        } else {
            CP_COMMIT();
        }
        GEMM_STAGE_MMA(&As[s * A_SZ], &Bs[s * B_SZ])
    }
    #undef M1_LOAD

    #pragma unroll
    for (int mt = 0; mt < 4; mt++) {
        int lmA = wm + mt * 16 + gid;
        int gmA = m0 + lmA, gmB = gmA + 8;
        #pragma unroll
        for (int nt = 0; nt < 4; nt++) {
            int n = wn + nt * 8 + tg * 2;
            float b0 = B1[e * FFd + n0 + n], b1 = B1[e * FFd + n0 + n + 1];
            if (gmA < cnt) {
                Y1[(size_t)(off + gmA) * FFd + n0 + n]     = gelu_exact(acc[mt][nt][0] + b0);
                Y1[(size_t)(off + gmA) * FFd + n0 + n + 1] = gelu_exact(acc[mt][nt][1] + b1);
            }
            if (gmB < cnt) {
                Y1[(size_t)(off + gmB) * FFd + n0 + n]     = gelu_exact(acc[mt][nt][2] + b0);
                Y1[(size_t)(off + gmB) * FFd + n0 + n + 1] = gelu_exact(acc[mt][nt][3] + b1);
            }
        }
    }
}

// ---------------- MoE GEMM2: out[t] += gelu(Y1 @ W2[e] + b2[e]) -------------
__global__ void moe2_tf32(const float* __restrict__ Y1,
                          const float* __restrict__ W2,
                          const float* __restrict__ B2,
                          float* __restrict__ OUT) {
    int e = blockIdx.z;
    int cnt = g_cnt[e];
    int m0 = blockIdx.y * 128;
    if (m0 >= cnt) return;
    int off = g_off[e];
    const float* B = W2 + (size_t)e * FFd * Dm;
    const int N = Dm, K = FFd;
    int n0 = blockIdx.x * 128;

    extern __shared__ unsigned smg[];
    unsigned* As = smg;
    unsigned* Bs = smg + NSTG * A_SZ;
    __shared__ int toks[128];

    int tid = threadIdx.x;
    int warp = tid >> 5, lane = tid & 31;
    int gid = lane >> 2, tg = lane & 3;
    int wm = (warp >> 2) * 64, wn = (warp & 3) * 32;
    if (tid < 128) {
        int m = m0 + tid;
        toks[tid] = (m < cnt) ? g_sorted[off + m] : -1;
    }
    __syncthreads();

    float acc[4][4][4];
    #pragma unroll
    for (int i = 0; i < 4; i++)
        #pragma unroll
        for (int j = 0; j < 4; j++)
            #pragma unroll
            for (int q = 0; q < 4; q++) acc[i][j][q] = 0.f;

    int raA = tid >> 3, caA = (tid & 7) * 4;
    int raB = tid >> 5, caB = (tid & 31) * 4;
    int ok[4];
    #pragma unroll
    for (int l = 0; l < 4; l++) ok[l] = (m0 + raA + l * 32) < cnt;

    #define M2_LOAD(st, gk)                                                        \
        _Pragma("unroll")                                                          \
        for (int l = 0; l < 4; l++) {                                              \
            int r = raA + l * 32;                                                  \
            cp16z(&As[(st) * A_SZ + r * ASTR + caA],                               \
                  Y1 + (size_t)(off + (ok[l] ? m0 + r : 0)) * FFd + (gk) + caA,    \
                  ok[l]);                                                          \
        }                                                                          \
        _Pragma("unroll")                                                          \
        for (int l = 0; l < 4; l++) {                                              \
            int r = raB + l * 8;                                                   \
            cp16(&Bs[(st) * B_SZ + r * BSTR + caB],                                \
                 B + (size_t)((gk) + r) * N + n0 + caB);                           \
        }                                                                          \
        CP_COMMIT();

    M2_LOAD(0, 0)
    M2_LOAD(1, BKt)

    int nk = K / BKt;
    for (int kt = 0; kt < nk; kt++) {
        int s = kt % NSTG;
        CP_WAIT1(); __syncthreads();
        if (kt + 2 < nk) {
            int st = (kt + 2) % NSTG;
            M2_LOAD(st, (kt + 2) * BKt)
        } else {
            CP_COMMIT();
        }
        GEMM_STAGE_MMA(&As[s * A_SZ], &Bs[s * B_SZ])
    }
    #undef M2_LOAD

    #pragma unroll
    for (int mt = 0; mt < 4; mt++) {
        int lmA = wm + mt * 16 + gid;
        int gmA = m0 + lmA, gmB = gmA + 8;
        int tA = toks[lmA], tB = toks[lmA + 8];
        #pragma unroll
        for (int nt = 0; nt < 4; nt++) {
            int n = wn + nt * 8 + tg * 2;
            float b0 = B2[e * Dm + n0 + n], b1 = B2[e * Dm + n0 + n + 1];
            if (gmA < cnt) {
                OUT[(size_t)tA * Dm + n0 + n]     += gelu_exact(acc[mt][nt][0] + b0);
                OUT[(size_t)tA * Dm + n0 + n + 1] += gelu_exact(acc[mt][nt][1] + b1);
            }
            if (gmB < cnt) {
                OUT[(size_t)tB * Dm + n0 + n]     += gelu_exact(acc[mt][nt][2] + b0);
                OUT[(size_t)tB * Dm + n0 + n + 1] += gelu_exact(acc[mt][nt][3] + b1);
            }
        }
    }
}

// =============================================================================
// Fused flash attention (unchanged from R6): per block = (b,h) x 64 Q rows.
// =============================================================================
#define QSTR 68
#define VSTR 72
#define FA_SMEM ((64 * QSTR + 64 * QSTR + 64 * VSTR) * 4)

__global__ void flash_tf32(const float* __restrict__ QKV, float* __restrict__ O) {
    extern __shared__ unsigned sm[];
    unsigned* Qs = sm;
    unsigned* Ks = sm + 64 * QSTR;
    unsigned* Vs = sm + 128 * QSTR;

    int bh = blockIdx.y;
    int b = bh / Hn, h = bh % Hn;
    int m0 = blockIdx.x * 64;
    int tid = threadIdx.x;
    int warp = tid >> 5, lane = tid & 31;
    int gid = lane >> 2, tg = lane & 3;
    int wm = warp * 16;

    #pragma unroll
    for (int l = 0; l < 8; l++) {
        int idx = tid + l * 128, r = idx >> 4, c4 = (idx & 15) * 4;
        cp16(&Qs[r * QSTR + c4],
             QKV + (size_t)(b * Sq + m0 + r) * 2304 + h * HDm + c4);
    }
    CP_COMMIT(); CP_WAIT0(); __syncthreads();

    unsigned aq[8][4];
    #pragma unroll
    for (int k8 = 0; k8 < 8; k8++) {
        int kb = k8 * 8;
        aq[k8][0] = t32(Qs[(wm + gid) * QSTR + kb + tg]);
        aq[k8][1] = t32(Qs[(wm + gid + 8) * QSTR + kb + tg]);
        aq[k8][2] = t32(Qs[(wm + gid) * QSTR + kb + tg + 4]);
        aq[k8][3] = t32(Qs[(wm + gid + 8) * QSTR + kb + tg + 4]);
    }
    __syncthreads();

    float mr0 = -1e30f, mr1 = -1e30f, lr0 = 0.f, lr1 = 0.f;
    float o[8][4];
    #pragma unroll
    for (int nt = 0; nt < 8; nt++)
        #pragma unroll
        for (int q = 0; q < 4; q++) o[nt][q] = 0.f;

    for (int n0 = 0; n0 < Sq; n0 += 64) {
        #pragma unroll
        for (int l = 0; l < 8; l++) {
            int idx = tid + l * 128, r = idx >> 4, c4 = (idx & 15) * 4;
            cp16(&Ks[r * QSTR + c4],
                 QKV + (size_t)(b * Sq + n0 + r) * 2304 + Dm + h * HDm + c4);
        }
        #pragma unroll
        for (int l = 0; l < 8; l++) {
            int idx = tid + l * 128, r = idx >> 4, c4 = (idx & 15) * 4;
            cp16(&Vs[r * VSTR + c4],
                 QKV + (size_t)(b * Sq + n0 + r) * 2304 + 2 * Dm + h * HDm + c4);
        }
        CP_COMMIT(); CP_WAIT0(); __syncthreads();

        float s[8][4];
        #pragma unroll
        for (int nt = 0; nt < 8; nt++)
            #pragma unroll
            for (int q = 0; q < 4; q++) s[nt][q] = 0.f;
        #pragma unroll
        for (int k8 = 0; k8 < 8; k8++) {
            int kb = k8 * 8;
            #pragma unroll
            for (int nt = 0; nt < 8; nt++) {
                int n = nt * 8 + gid;
                unsigned b0 = t32(Ks[n * QSTR + kb + tg]);
                unsigned b1 = t32(Ks[n * QSTR + kb + tg + 4]);
                mma_tf32(s[nt], aq[k8][0], aq[k8][1], aq[k8][2], aq[k8][3], b0, b1);
            }
        }

        const float sc = 0.125f;
        float mx0 = -1e30f, mx1 = -1e30f;
        #pragma unroll
        for (int nt = 0; nt < 8; nt++) {
            s[nt][0] *= sc; s[nt][1] *= sc; s[nt][2] *= sc; s[nt][3] *= sc;
            mx0 = fmaxf(mx0, fmaxf(s[nt][0], s[nt][1]));
            mx1 = fmaxf(mx1, fmaxf(s[nt][2], s[nt][3]));
        }
        mx0 = fmaxf(mx0, __shfl_xor_sync(0xffffffffu, mx0, 1));
        mx0 = fmaxf(mx0, __shfl_xor_sync(0xffffffffu, mx0, 2));
        mx1 = fmaxf(mx1, __shfl_xor_sync(0xffffffffu, mx1, 1));
        mx1 = fmaxf(mx1, __shfl_xor_sync(0xffffffffu, mx1, 2));
        float mn0 = fmaxf(mr0, mx0), mn1 = fmaxf(mr1, mx1);
        float a0 = __expf(mr0 - mn0), a1 = __expf(mr1 - mn1);
        float sum0 = 0.f, sum1 = 0.f;
        #pragma unroll
        for (int nt = 0; nt < 8; nt++) {
            s[nt][0] = __expf(s[nt][0] - mn0);
            s[nt][1] = __expf(s[nt][1] - mn0);
            s[nt][2] = __expf(s[nt][2] - mn1);
            s[nt][3] = __expf(s[nt][3] - mn1);
            sum0 += s[nt][0] + s[nt][1];
            sum1 += s[nt][2] + s[nt][3];
        }
        sum0 += __shfl_xor_sync(0xffffffffu, sum0, 1);
        sum0 += __shfl_xor_sync(0xffffffffu, sum0, 2);
        sum1 += __shfl_xor_sync(0xffffffffu, sum1, 1);
        sum1 += __shfl_xor_sync(0xffffffffu, sum1, 2);
        lr0 = lr0 * a0 + sum0;
        lr1 = lr1 * a1 + sum1;
        mr0 = mn0; mr1 = mn1;
        #pragma unroll
        for (int nt = 0; nt < 8; nt++) {
            o[nt][0] *= a0; o[nt][1] *= a0;
            o[nt][2] *= a1; o[nt][3] *= a1;
        }

        unsigned* Ps = Qs;
        #pragma unroll
        for (int nt = 0; nt < 8; nt++) {
            int c = nt * 8 + tg * 2;
            Ps[(wm + gid) * QSTR + c]         = f2t(s[nt][0]);
            Ps[(wm + gid) * QSTR + c + 1]     = f2t(s[nt][1]);
            Ps[(wm + gid + 8) * QSTR + c]     = f2t(s[nt][2]);
            Ps[(wm + gid + 8) * QSTR + c + 1] = f2t(s[nt][3]);
        }
        __syncwarp();

        #pragma unroll
        for (int kb = 0; kb < 64; kb += 8) {
            unsigned p0 = Ps[(wm + gid) * QSTR + kb + tg];
            unsigned p1 = Ps[(wm + gid + 8) * QSTR + kb + tg];
            unsigned p2 = Ps[(wm + gid) * QSTR + kb + tg + 4];
            unsigned p3 = Ps[(wm + gid + 8) * QSTR + kb + tg + 4];
            #pragma unroll
            for (int nt = 0; nt < 8; nt++) {
                int n = nt * 8 + gid;
                unsigned v0 = t32(Vs[(kb + tg) * VSTR + n]);
                unsigned v1 = t32(Vs[(kb + tg + 4) * VSTR + n]);
                mma_tf32(o[nt], p0, p1, p2, p3, v0, v1);
            }
        }
        __syncthreads();
    }

    float inv0 = 1.0f / lr0, inv1 = 1.0f / lr1;
    int rA = b * Sq + m0 + wm + gid, rB = rA + 8;
    #pragma unroll
    for (int nt = 0; nt < 8; nt++) {
        int c = h * HDm + nt * 8 + tg * 2;
        O[(size_t)rA * Dm + c]     = o[nt][0] * inv0;
        O[(size_t)rA * Dm + c + 1] = o[nt][1] * inv0;
        O[(size_t)rB * Dm + c]     = o[nt][2] * inv1;
        O[(size_t)rB * Dm + c + 1] = o[nt][3] * inv1;
    }
}

// ---------------- router ------------------------------------------------------
__global__ void route_kernel(const float* __restrict__ H2,
                             const float* __restrict__ SW,
                             const float* __restrict__ SB) {
    int warp = (blockIdx.x * blockDim.x + threadIdx.x) >> 5;
    int lane = threadIdx.x & 31;
    if (warp >= TOK) return;
    const float* hrow = H2 + (size_t)warp * Dm;
    float acc[En];
    #pragma unroll
    for (int e = 0; e < En; e++) acc[e] = 0.f;
    for (int d = lane; d < Dm; d += 32) {
        float hv = hrow[d];
        const float* w = SW + d * En;
        #pragma unroll
        for (int e = 0; e < En; e++) acc[e] += hv * w[e];
    }
    #pragma unroll
    for (int e = 0; e < En; e++)
        #pragma unroll
        for (int o = 16; o; o >>= 1)
            acc[e] += __shfl_xor_sync(0xffffffffu, acc[e], o);
    if (lane == 0) {
        float best = acc[0] + SB[0];
        int be = 0;
        #pragma unroll
        for (int e = 1; e < En; e++) {
            float v = acc[e] + SB[e];
            if (v > best) { best = v; be = e; }
        }
        g_routes[warp] = be;
        atomicAdd(&g_cnt[be], 1);
    }
}

__global__ void offsets_kernel() {
    if (threadIdx.x == 0) {
        int acc = 0;
        for (int e = 0; e < En; e++) { g_off[e] = acc; acc += g_cnt[e]; }
    }
}

__global__ void scatter_kernel() {
    int t = blockIdx.x * blockDim.x + threadIdx.x;
    if (t >= TOK) return;
    int e = g_routes[t];
    int pos = atomicAdd(&g_cur[e], 1);
    g_sorted[g_off[e] + pos] = t;
}

// ---------------- launch ------------------------------------------------------
extern "C" void kernel_launch(void* const* d_in, const int* in_sizes, int n_in,
                              void* d_out, int out_size) {
    const float* x       = (const float*)d_in[0];
    // d_in[1] = indexes_list (unused by reference math)
    const float* ln1_g   = (const float*)d_in[2];
    const float* ln1_b   = (const float*)d_in[3];
    const float* qkv_w   = (const float*)d_in[4];
    const float* proj_w  = (const float*)d_in[5];
    const float* proj_b  = (const float*)d_in[6];
    const float* ln2_g   = (const float*)d_in[7];
    const float* ln2_b   = (const float*)d_in[8];
    const float* sw_w    = (const float*)d_in[9];
    const float* sw_b    = (const float*)d_in[10];
    const float* w1      = (const float*)d_in[11];
    const float* b1      = (const float*)d_in[12];
    const float* w2      = (const float*)d_in[13];
    const float* b2      = (const float*)d_in[14];
    float* out = (float*)d_out;

    float *gh, *gqkv, *go, *gh2, *gy1;
    cudaGetSymbolAddress((void**)&gh,   g_h);
    cudaGetSymbolAddress((void**)&gqkv, g_qkv);
    cudaGetSymbolAddress((void**)&go,   g_o);
    cudaGetSymbolAddress((void**)&gh2,  g_h2);
    cudaGetSymbolAddress((void**)&gy1,  g_y1);

    static int smem_set = 0;
    if (!smem_set) {
        cudaFuncSetAttribute(flash_tf32, cudaFuncAttributeMaxDynamicSharedMemorySize, FA_SMEM);
        cudaFuncSetAttribute(gemm_tf32,  cudaFuncAttributeMaxDynamicSharedMemorySize, GEMM_SMEM);
        cudaFuncSetAttribute(moe1_tf32,  cudaFuncAttributeMaxDynamicSharedMemorySize, GEMM_SMEM);
        cudaFuncSetAttribute(moe2_tf32,  cudaFuncAttributeMaxDynamicSharedMemorySize, GEMM_SMEM);
        smem_set = 1;
    }

    reset_kernel<<<1, 32>>>();

    // ln1
    ln_kernel<<<TOK, 256>>>(x, ln1_g, ln1_b, gh);
    // qkv = h @ qkv_w   [4096 x 2304]
    gemm_tf32<<<dim3(2304 / 128, TOK / 128), 256, GEMM_SMEM>>>(gh, qkv_w, gqkv,
                                                               TOK, 2304, Dm, nullptr, nullptr);
    // fused attention
    flash_tf32<<<dim3(Sq / 64, BHN), 128, FA_SMEM>>>(gqkv, go);
    // xmid = x + o @ proj_w + proj_b   -> d_out
    gemm_tf32<<<dim3(Dm / 128, TOK / 128), 256, GEMM_SMEM>>>(go, proj_w, out,
                                                             TOK, Dm, Dm, proj_b, x);
    // ln2
    ln_kernel<<<TOK, 256>>>(out, ln2_g, ln2_b, gh2);
    // routing
    route_kernel<<<512, 256>>>(gh2, sw_w, sw_b);
    offsets_kernel<<<1, 32>>>();
    scatter_kernel<<<TOK / 256, 256>>>();
    // MoE expert GEMMs
    moe1_tf32<<<dim3(FFd / 128, TOK / 128, En), 256, GEMM_SMEM>>>(gh2, w1, b1, gy1);
    moe2_tf32<<<dim3(Dm / 128, TOK / 128, En), 256, GEMM_SMEM>>>(gy1, w2, b2, out);
}

// round 8
// speedup vs baseline: 1.5133x; 1.0494x over previous
#include <cuda_runtime.h>
#include <math.h>

#define Bsz 8
#define Sq  512
#define Dm  768
#define Hn  12
#define HDm 64
#define En  8
#define FFd 3072
#define TOK 4096
#define BHN 96

// ---------------- scratch (device globals; no allocations allowed) ----------
__device__ float g_h[TOK * Dm];
__device__ float g_qkv[TOK * 3 * Dm];
__device__ float g_o[TOK * Dm];
__device__ float g_h2[TOK * Dm];
__device__ float g_y1[(size_t)TOK * FFd];
__device__ int   g_routes[TOK];
__device__ int   g_cnt[En];
__device__ int   g_off[En];
__device__ int   g_cur[En];
__device__ int   g_sorted[TOK];

// ---------------- helpers ---------------------------------------------------
__device__ __forceinline__ float gelu_exact(float x) {
    return 0.5f * x * (1.0f + erff(x * 0.70710678118654752f));
}

__device__ __forceinline__ unsigned f2t(float f) {
    unsigned u;
    asm("cvt.rna.tf32.f32 %0, %1;" : "=r"(u) : "f"(f));
    return u;
}
__device__ __forceinline__ unsigned t32(unsigned u) {
    return f2t(__uint_as_float(u));
}
__device__ __forceinline__ float rtf(float f) {       // round float to tf32 grid
    return __uint_as_float(f2t(f));
}
template<bool C> __device__ __forceinline__ unsigned cva(unsigned u) {
    return C ? t32(u) : u;
}

__device__ __forceinline__ void mma_tf32(float c[4],
                                         unsigned a0, unsigned a1, unsigned a2, unsigned a3,
                                         unsigned b0, unsigned b1) {
    asm volatile(
        "mma.sync.aligned.m16n8k8.row.col.f32.tf32.tf32.f32 "
        "{%0,%1,%2,%3},{%4,%5,%6,%7},{%8,%9},{%0,%1,%2,%3};"
        : "+f"(c[0]), "+f"(c[1]), "+f"(c[2]), "+f"(c[3])
        : "r"(a0), "r"(a1), "r"(a2), "r"(a3), "r"(b0), "r"(b1));
}

__device__ __forceinline__ void cp16(unsigned* d, const void* s) {
    unsigned sd = (unsigned)__cvta_generic_to_shared(d);
    asm volatile("cp.async.cg.shared.global [%0], [%1], 16;" :: "r"(sd), "l"(s));
}
__device__ __forceinline__ void cp16z(unsigned* d, const void* s, int pred) {
    unsigned sd = (unsigned)__cvta_generic_to_shared(d);
    int sz = pred ? 16 : 0;
    asm volatile("cp.async.cg.shared.global [%0], [%1], 16, %2;" :: "r"(sd), "l"(s), "r"(sz));
}
#define CP_COMMIT() asm volatile("cp.async.commit_group;")
#define CP_WAIT0()  asm volatile("cp.async.wait_group 0;")
#define CP_WAIT1()  asm volatile("cp.async.wait_group 1;")

// ---------------- reset counters --------------------------------------------
__global__ void reset_kernel() {
    int t = threadIdx.x;
    if (t < En) { g_cnt[t] = 0; g_cur[t] = 0; }
}

// ---------------- layernorm (optionally tf32-rounded output) ----------------
__global__ void ln_kernel(const float* __restrict__ X,
                          const float* __restrict__ gam,
                          const float* __restrict__ bet,
                          float* __restrict__ Y, int rnd) {
    int row = blockIdx.x;
    int tid = threadIdx.x;
    const float* x = X + (size_t)row * Dm;
    float v0 = x[tid], v1 = x[tid + 256], v2 = x[tid + 512];

    __shared__ float red[256];
    red[tid] = v0 + v1 + v2; __syncthreads();
    #pragma unroll
    for (int st = 128; st > 0; st >>= 1) {
        if (tid < st) red[tid] += red[tid + st];
        __syncthreads();
    }
    float mu = red[0] / (float)Dm;
    __syncthreads();

    float d0 = v0 - mu, d1 = v1 - mu, d2 = v2 - mu;
    red[tid] = d0 * d0 + d1 * d1 + d2 * d2; __syncthreads();
    #pragma unroll
    for (int st = 128; st > 0; st >>= 1) {
        if (tid < st) red[tid] += red[tid + st];
        __syncthreads();
    }
    float rstd = rsqrtf(red[0] / (float)Dm + 1e-5f);

    float* y = Y + (size_t)row * Dm;
    float o0 = d0 * rstd * gam[tid]       + bet[tid];
    float o1 = d1 * rstd * gam[tid + 256] + bet[tid + 256];
    float o2 = d2 * rstd * gam[tid + 512] + bet[tid + 512];
    if (rnd) { o0 = rtf(o0); o1 = rtf(o1); o2 = rtf(o2); }
    y[tid] = o0; y[tid + 256] = o1; y[tid + 512] = o2;
}

// =============================================================================
// tf32 GEMM: BM=128, BN=128, BK=32, 3-stage cp.async ring, 256 thr = 8 warps.
// CVTA: cvt A fragments (false when A is pre-rounded). ROUT: round output.
// =============================================================================
#define BKt  32
#define ASTR 36
#define BSTR 136
#define A_SZ (128 * ASTR)
#define B_SZ (BKt * BSTR)
#define NSTG 3
#define GEMM_SMEM (NSTG * (A_SZ + B_SZ) * 4)

#define GEMM_STAGE_MMA(Asb, Bsb, CVTA)                                         \
    _Pragma("unroll")                                                          \
    for (int ks = 0; ks < 4; ks++) {                                           \
        int kb = ks * 8;                                                       \
        unsigned af[4][4], bf[4][2];                                           \
        _Pragma("unroll")                                                      \
        for (int mt = 0; mt < 4; mt++) {                                       \
            int m = wm + mt * 16 + gid;                                        \
            af[mt][0] = cva<CVTA>((Asb)[m * ASTR + kb + tg]);                  \
            af[mt][1] = cva<CVTA>((Asb)[(m + 8) * ASTR + kb + tg]);            \
            af[mt][2] = cva<CVTA>((Asb)[m * ASTR + kb + tg + 4]);              \
            af[mt][3] = cva<CVTA>((Asb)[(m + 8) * ASTR + kb + tg + 4]);        \
        }                                                                      \
        _Pragma("unroll")                                                      \
        for (int nt = 0; nt < 4; nt++) {                                       \
            int n = wn + nt * 8 + gid;                                         \
            bf[nt][0] = t32((Bsb)[(kb + tg) * BSTR + n]);                      \
            bf[nt][1] = t32((Bsb)[(kb + tg + 4) * BSTR + n]);                  \
        }                                                                      \
        _Pragma("unroll")                                                      \
        for (int mt = 0; mt < 4; mt++)                                         \
            _Pragma("unroll")                                                  \
            for (int nt = 0; nt < 4; nt++)                                     \
                mma_tf32(acc[mt][nt], af[mt][0], af[mt][1], af[mt][2],         \
                         af[mt][3], bf[nt][0], bf[nt][1]);                     \
    }

template<bool CVTA, bool ROUT>
__global__ void gemm_tf32(const float* __restrict__ A, const float* __restrict__ B,
                          float* __restrict__ C, int M, int N, int K,
                          const float* __restrict__ bias,
                          const float* __restrict__ resid) {
    extern __shared__ unsigned smg[];
    unsigned* As = smg;
    unsigned* Bs = smg + NSTG * A_SZ;

    int tid = threadIdx.x;
    int warp = tid >> 5, lane = tid & 31;
    int gid = lane >> 2, tg = lane & 3;
    int wm = (warp >> 2) * 64, wn = (warp & 3) * 32;
    int m0 = blockIdx.y * 128, n0 = blockIdx.x * 128;

    float acc[4][4][4];
    #pragma unroll
    for (int i = 0; i < 4; i++)
        #pragma unroll
        for (int j = 0; j < 4; j++)
            #pragma unroll
            for (int q = 0; q < 4; q++) acc[i][j][q] = 0.f;

    int raA = tid >> 3, caA = (tid & 7) * 4;
    int raB = tid >> 5, caB = (tid & 31) * 4;

    #define G_LOAD(st, gk)                                                         \
        _Pragma("unroll")                                                          \
        for (int l = 0; l < 4; l++) {                                              \
            int r = raA + l * 32;                                                  \
            cp16(&As[(st) * A_SZ + r * ASTR + caA],                                \
                 A + (size_t)(m0 + r) * K + (gk) + caA);                           \
        }                                                                          \
        _Pragma("unroll")                                                          \
        for (int l = 0; l < 4; l++) {                                              \
            int r = raB + l * 8;                                                   \
            cp16(&Bs[(st) * B_SZ + r * BSTR + caB],                                \
                 B + (size_t)((gk) + r) * N + n0 + caB);                           \
        }                                                                          \
        CP_COMMIT();

    G_LOAD(0, 0)
    G_LOAD(1, BKt)

    int nk = K / BKt;
    for (int kt = 0; kt < nk; kt++) {
        int s = kt % NSTG;
        CP_WAIT1(); __syncthreads();
        if (kt + 2 < nk) {
            int st = (kt + 2) % NSTG;
            G_LOAD(st, (kt + 2) * BKt)
        } else {
            CP_COMMIT();
        }
        GEMM_STAGE_MMA(&As[s * A_SZ], &Bs[s * B_SZ], CVTA)
    }
    #undef G_LOAD

    #pragma unroll
    for (int mt = 0; mt < 4; mt++) {
        int mA = m0 + wm + mt * 16 + gid, mB = mA + 8;
        #pragma unroll
        for (int nt = 0; nt < 4; nt++) {
            int n = n0 + wn + nt * 8 + tg * 2;
            float v0 = acc[mt][nt][0], v1 = acc[mt][nt][1];
            float v2 = acc[mt][nt][2], v3 = acc[mt][nt][3];
            if (bias) {
                float b0 = bias[n], b1 = bias[n + 1];
                v0 += b0; v1 += b1; v2 += b0; v3 += b1;
            }
            if (resid) {
                v0 += resid[(size_t)mA * N + n];
                v1 += resid[(size_t)mA * N + n + 1];
                v2 += resid[(size_t)mB * N + n];
                v3 += resid[(size_t)mB * N + n + 1];
            }
            if (ROUT) { v0 = rtf(v0); v1 = rtf(v1); v2 = rtf(v2); v3 = rtf(v3); }
            C[(size_t)mA * N + n]     = v0;
            C[(size_t)mA * N + n + 1] = v1;
            C[(size_t)mB * N + n]     = v2;
            C[(size_t)mB * N + n + 1] = v3;
        }
    }
}

// ---------------- MoE GEMM1: Y1 = round(gelu(gather(H2) @ W1[e] + b1[e])) ---
__global__ void moe1_tf32(const float* __restrict__ H2,
                          const float* __restrict__ W1,
                          const float* __restrict__ B1,
                          float* __restrict__ Y1) {
    int e = blockIdx.z;
    int cnt = g_cnt[e];
    int m0 = blockIdx.y * 128;
    if (m0 >= cnt) return;
    int off = g_off[e];
    const float* B = W1 + (size_t)e * Dm * FFd;
    const int N = FFd, K = Dm;
    int n0 = blockIdx.x * 128;

    extern __shared__ unsigned smg[];
    unsigned* As = smg;
    unsigned* Bs = smg + NSTG * A_SZ;
    __shared__ int toks[128];

    int tid = threadIdx.x;
    int warp = tid >> 5, lane = tid & 31;
    int gid = lane >> 2, tg = lane & 3;
    int wm = (warp >> 2) * 64, wn = (warp & 3) * 32;
    if (tid < 128) {
        int m = m0 + tid;
        toks[tid] = (m < cnt) ? g_sorted[off + m] : -1;
    }
    __syncthreads();

    float acc[4][4][4];
    #pragma unroll
    for (int i = 0; i < 4; i++)
        #pragma unroll
        for (int j = 0; j < 4; j++)
            #pragma unroll
            for (int q = 0; q < 4; q++) acc[i][j][q] = 0.f;

    int raA = tid >> 3, caA = (tid & 7) * 4;
    int raB = tid >> 5, caB = (tid & 31) * 4;
    int tk[4];
    #pragma unroll
    for (int l = 0; l < 4; l++) tk[l] = toks[raA + l * 32];

    #define M1_LOAD(st, gk)                                                        \
        _Pragma("unroll")                                                          \
        for (int l = 0; l < 4; l++) {                                              \
            int r = raA + l * 32;                                                  \
            cp16z(&As[(st) * A_SZ + r * ASTR + caA],                               \
                  H2 + (size_t)(tk[l] >= 0 ? tk[l] : 0) * Dm + (gk) + caA,         \
                  tk[l] >= 0);                                                     \
        }                                                                          \
        _Pragma("unroll")                                                          \
        for (int l = 0; l < 4; l++) {                                              \
            int r = raB + l * 8;                                                   \
            cp16(&Bs[(st) * B_SZ + r * BSTR + caB],                                \
                 B + (size_t)((gk) + r) * N + n0 + caB);                           \
        }                                                                          \
        CP_COMMIT();

    M1_LOAD(0, 0)
    M1_LOAD(1, BKt)

    int nk = K / BKt;
    for (int kt = 0; kt < nk; kt++) {
        int s = kt % NSTG;
        CP_WAIT1(); __syncthreads();
        if (kt + 2 < nk) {
            int st = (kt + 2) % NSTG;
            M1_LOAD(st, (kt + 2) * BKt)
        } else {
            CP_COMMIT();
        }
        GEMM_STAGE_MMA(&As[s * A_SZ], &Bs[s * B_SZ], true)
    }
    #undef M1_LOAD

    #pragma unroll
    for (int mt = 0; mt < 4; mt++) {
        int lmA = wm + mt * 16 + gid;
        int gmA = m0 + lmA, gmB = gmA + 8;
        #pragma unroll
        for (int nt = 0; nt < 4; nt++) {
            int n = wn + nt * 8 + tg * 2;
            float b0 = B1[e * FFd + n0 + n], b1 = B1[e * FFd + n0 + n + 1];
            if (gmA < cnt) {
                Y1[(size_t)(off + gmA) * FFd + n0 + n]     = rtf(gelu_exact(acc[mt][nt][0] + b0));
                Y1[(size_t)(off + gmA) * FFd + n0 + n + 1] = rtf(gelu_exact(acc[mt][nt][1] + b1));
            }
            if (gmB < cnt) {
                Y1[(size_t)(off + gmB) * FFd + n0 + n]     = rtf(gelu_exact(acc[mt][nt][2] + b0));
                Y1[(size_t)(off + gmB) * FFd + n0 + n + 1] = rtf(gelu_exact(acc[mt][nt][3] + b1));
            }
        }
    }
}

// ---------------- MoE GEMM2: out[t] += gelu(Y1 @ W2[e] + b2[e]) -------------
__global__ void moe2_tf32(const float* __restrict__ Y1,
                          const float* __restrict__ W2,
                          const float* __restrict__ B2,
                          float* __restrict__ OUT) {
    int e = blockIdx.z;
    int cnt = g_cnt[e];
    int m0 = blockIdx.y * 128;
    if (m0 >= cnt) return;
    int off = g_off[e];
    const float* B = W2 + (size_t)e * FFd * Dm;
    const int N = Dm, K = FFd;
    int n0 = blockIdx.x * 128;

    extern __shared__ unsigned smg[];
    unsigned* As = smg;
    unsigned* Bs = smg + NSTG * A_SZ;
    __shared__ int toks[128];

    int tid = threadIdx.x;
    int warp = tid >> 5, lane = tid & 31;
    int gid = lane >> 2, tg = lane & 3;
    int wm = (warp >> 2) * 64, wn = (warp & 3) * 32;
    if (tid < 128) {
        int m = m0 + tid;
        toks[tid] = (m < cnt) ? g_sorted[off + m] : -1;
    }
    __syncthreads();

    float acc[4][4][4];
    #pragma unroll
    for (int i = 0; i < 4; i++)
        #pragma unroll
        for (int j = 0; j < 4; j++)
            #pragma unroll
            for (int q = 0; q < 4; q++) acc[i][j][q] = 0.f;

    int raA = tid >> 3, caA = (tid & 7) * 4;
    int raB = tid >> 5, caB = (tid & 31) * 4;
    int ok[4];
    #pragma unroll
    for (int l = 0; l < 4; l++) ok[l] = (m0 + raA + l * 32) < cnt;

    #define M2_LOAD(st, gk)                                                        \
        _Pragma("unroll")                                                          \
        for (int l = 0; l < 4; l++) {                                              \
            int r = raA + l * 32;                                                  \
            cp16z(&As[(st) * A_SZ + r * ASTR + caA],                               \
                  Y1 + (size_t)(off + (ok[l] ? m0 + r : 0)) * FFd + (gk) + caA,    \
                  ok[l]);                                                          \
        }                                                                          \
        _Pragma("unroll")                                                          \
        for (int l = 0; l < 4; l++) {                                              \
            int r = raB + l * 8;                                                   \
            cp16(&Bs[(st) * B_SZ + r * BSTR + caB],                                \
                 B + (size_t)((gk) + r) * N + n0 + caB);                           \
        }                                                                          \
        CP_COMMIT();

    M2_LOAD(0, 0)
    M2_LOAD(1, BKt)

    int nk = K / BKt;
    for (int kt = 0; kt < nk; kt++) {
        int s = kt % NSTG;
        CP_WAIT1(); __syncthreads();
        if (kt + 2 < nk) {
            int st = (kt + 2) % NSTG;
            M2_LOAD(st, (kt + 2) * BKt)
        } else {
            CP_COMMIT();
        }
        GEMM_STAGE_MMA(&As[s * A_SZ], &Bs[s * B_SZ], false)   // Y1 pre-rounded
    }
    #undef M2_LOAD

    #pragma unroll
    for (int mt = 0; mt < 4; mt++) {
        int lmA = wm + mt * 16 + gid;
        int gmA = m0 + lmA, gmB = gmA + 8;
        int tA = toks[lmA], tB = toks[lmA + 8];
        #pragma unroll
        for (int nt = 0; nt < 4; nt++) {
            int n = wn + nt * 8 + tg * 2;
            float b0 = B2[e * Dm + n0 + n], b1 = B2[e * Dm + n0 + n + 1];
            if (gmA < cnt) {
                OUT[(size_t)tA * Dm + n0 + n]     += gelu_exact(acc[mt][nt][0] + b0);
                OUT[(size_t)tA * Dm + n0 + n + 1] += gelu_exact(acc[mt][nt][1] + b1);
            }
            if (gmB < cnt) {
                OUT[(size_t)tB * Dm + n0 + n]     += gelu_exact(acc[mt][nt][2] + b0);
                OUT[(size_t)tB * Dm + n0 + n + 1] += gelu_exact(acc[mt][nt][3] + b1);
            }
        }
    }
}

// =============================================================================
// Fused flash attention, K/V double-buffered. QKV is pre-rounded tf32 (raw
// bits feed mma directly). Per block = (b,h) x 64 Q rows, 128 thr = 4 warps.
// =============================================================================
#define QSTR 68
#define VSTR 72
#define FA_SMEM ((64 * QSTR + 2 * 64 * QSTR + 2 * 64 * VSTR) * 4)

__global__ void flash_tf32(const float* __restrict__ QKV, float* __restrict__ O) {
    extern __shared__ unsigned sm[];
    unsigned* Qs = sm;                         // 64 x QSTR (reused as P)
    unsigned* Ks = sm + 64 * QSTR;             // 2 x 64 x QSTR
    unsigned* Vs = sm + 64 * QSTR + 2 * 64 * QSTR;  // 2 x 64 x VSTR

    int bh = blockIdx.y;
    int b = bh / Hn, h = bh % Hn;
    int m0 = blockIdx.x * 64;
    int tid = threadIdx.x;
    int warp = tid >> 5, lane = tid & 31;
    int gid = lane >> 2, tg = lane & 3;
    int wm = warp * 16;

    // --- load Q tile ---
    #pragma unroll
    for (int l = 0; l < 8; l++) {
        int idx = tid + l * 128, r = idx >> 4, c4 = (idx & 15) * 4;
        cp16(&Qs[r * QSTR + c4],
             QKV + (size_t)(b * Sq + m0 + r) * 2304 + h * HDm + c4);
    }
    CP_COMMIT(); CP_WAIT0(); __syncthreads();

    unsigned aq[8][4];
    #pragma unroll
    for (int k8 = 0; k8 < 8; k8++) {
        int kb = k8 * 8;
        aq[k8][0] = Qs[(wm + gid) * QSTR + kb + tg];
        aq[k8][1] = Qs[(wm + gid + 8) * QSTR + kb + tg];
        aq[k8][2] = Qs[(wm + gid) * QSTR + kb + tg + 4];
        aq[k8][3] = Qs[(wm + gid + 8) * QSTR + kb + tg + 4];
    }
    __syncthreads();  // Qs free -> P staging

    #define FA_LOAD_KV(chunk, buf)                                                 \
        _Pragma("unroll")                                                          \
        for (int l = 0; l < 8; l++) {                                              \
            int idx = tid + l * 128, r = idx >> 4, c4 = (idx & 15) * 4;            \
            cp16(&Ks[(buf) * 64 * QSTR + r * QSTR + c4],                           \
                 QKV + (size_t)(b * Sq + (chunk) * 64 + r) * 2304 + Dm + h * HDm + c4); \
        }                                                                          \
        _Pragma("unroll")                                                          \
        for (int l = 0; l < 8; l++) {                                              \
            int idx = tid + l * 128, r = idx >> 4, c4 = (idx & 15) * 4;            \
            cp16(&Vs[(buf) * 64 * VSTR + r * VSTR + c4],                           \
                 QKV + (size_t)(b * Sq + (chunk) * 64 + r) * 2304 + 2 * Dm + h * HDm + c4); \
        }                                                                          \
        CP_COMMIT();

    float mr0 = -1e30f, mr1 = -1e30f, lr0 = 0.f, lr1 = 0.f;
    float o[8][4];
    #pragma unroll
    for (int nt = 0; nt < 8; nt++)
        #pragma unroll
        for (int q = 0; q < 4; q++) o[nt][q] = 0.f;

    FA_LOAD_KV(0, 0)

    for (int c = 0; c < 8; c++) {
        int buf = c & 1;
        if (c + 1 < 8) {
            FA_LOAD_KV(c + 1, buf ^ 1)
            CP_WAIT1();
        } else {
            CP_WAIT0();
        }
        __syncthreads();
        unsigned* Kb = Ks + buf * 64 * QSTR;
        unsigned* Vb = Vs + buf * 64 * VSTR;

        // --- S = Q @ K^T ---
        float s[8][4];
        #pragma unroll
        for (int nt = 0; nt < 8; nt++)
            #pragma unroll
            for (int q = 0; q < 4; q++) s[nt][q] = 0.f;
        #pragma unroll
        for (int k8 = 0; k8 < 8; k8++) {
            int kb = k8 * 8;
            #pragma unroll
            for (int nt = 0; nt < 8; nt++) {
                int n = nt * 8 + gid;
                unsigned b0 = Kb[n * QSTR + kb + tg];
                unsigned b1 = Kb[n * QSTR + kb + tg + 4];
                mma_tf32(s[nt], aq[k8][0], aq[k8][1], aq[k8][2], aq[k8][3], b0, b1);
            }
        }

        // --- online softmax ---
        const float sc = 0.125f;
        float mx0 = -1e30f, mx1 = -1e30f;
        #pragma unroll
        for (int nt = 0; nt < 8; nt++) {
            s[nt][0] *= sc; s[nt][1] *= sc; s[nt][2] *= sc; s[nt][3] *= sc;
            mx0 = fmaxf(mx0, fmaxf(s[nt][0], s[nt][1]));
            mx1 = fmaxf(mx1, fmaxf(s[nt][2], s[nt][3]));
        }
        mx0 = fmaxf(mx0, __shfl_xor_sync(0xffffffffu, mx0, 1));
        mx0 = fmaxf(mx0, __shfl_xor_sync(0xffffffffu, mx0, 2));
        mx1 = fmaxf(mx1, __shfl_xor_sync(0xffffffffu, mx1, 1));
        mx1 = fmaxf(mx1, __shfl_xor_sync(0xffffffffu, mx1, 2));
        float mn0 = fmaxf(mr0, mx0), mn1 = fmaxf(mr1, mx1);
        float a0 = __expf(mr0 - mn0), a1 = __expf(mr1 - mn1);
        float sum0 = 0.f, sum1 = 0.f;
        #pragma unroll
        for (int nt = 0; nt < 8; nt++) {
            s[nt][0] = __expf(s[nt][0] - mn0);
            s[nt][1] = __expf(s[nt][1] - mn0);
            s[nt][2] = __expf(s[nt][2] - mn1);
            s[nt][3] = __expf(s[nt][3] - mn1);
            sum0 += s[nt][0] + s[nt][1];
            sum1 += s[nt][2] + s[nt][3];
        }
        sum0 += __shfl_xor_sync(0xffffffffu, sum0, 1);
        sum0 += __shfl_xor_sync(0xffffffffu, sum0, 2);
        sum1 += __shfl_xor_sync(0xffffffffu, sum1, 1);
        sum1 += __shfl_xor_sync(0xffffffffu, sum1, 2);
        lr0 = lr0 * a0 + sum0;
        lr1 = lr1 * a1 + sum1;
        mr0 = mn0; mr1 = mn1;
        #pragma unroll
        for (int nt = 0; nt < 8; nt++) {
            o[nt][0] *= a0; o[nt][1] *= a0;
            o[nt][2] *= a1; o[nt][3] *= a1;
        }

        // --- stage P into smem as tf32 (warp-local rows) ---
        unsigned* Ps = Qs;
        #pragma unroll
        for (int nt = 0; nt < 8; nt++) {
            int cc = nt * 8 + tg * 2;
            Ps[(wm + gid) * QSTR + cc]         = f2t(s[nt][0]);
            Ps[(wm + gid) * QSTR + cc + 1]     = f2t(s[nt][1]);
            Ps[(wm + gid + 8) * QSTR + cc]     = f2t(s[nt][2]);
            Ps[(wm + gid + 8) * QSTR + cc + 1] = f2t(s[nt][3]);
        }
        __syncwarp();

        // --- O += P @ V ---
        #pragma unroll
        for (int kb = 0; kb < 64; kb += 8) {
            unsigned p0 = Ps[(wm + gid) * QSTR + kb + tg];
            unsigned p1 = Ps[(wm + gid + 8) * QSTR + kb + tg];
            unsigned p2 = Ps[(wm + gid) * QSTR + kb + tg + 4];
            unsigned p3 = Ps[(wm + gid + 8) * QSTR + kb + tg + 4];
            #pragma unroll
            for (int nt = 0; nt < 8; nt++) {
                int n = nt * 8 + gid;
                unsigned v0 = Vb[(kb + tg) * VSTR + n];
                unsigned v1 = Vb[(kb + tg + 4) * VSTR + n];
                mma_tf32(o[nt], p0, p1, p2, p3, v0, v1);
            }
        }
        __syncthreads();  // all warps done reading buf before it is refilled
    }
    #undef FA_LOAD_KV

    // --- epilogue: O /= l, tf32-rounded (feeds proj GEMM A) ---
    float inv0 = 1.0f / lr0, inv1 = 1.0f / lr1;
    int rA = b * Sq + m0 + wm + gid, rB = rA + 8;
    #pragma unroll
    for (int nt = 0; nt < 8; nt++) {
        int cc = h * HDm + nt * 8 + tg * 2;
        O[(size_t)rA * Dm + cc]     = rtf(o[nt][0] * inv0);
        O[(size_t)rA * Dm + cc + 1] = rtf(o[nt][1] * inv0);
        O[(size_t)rB * Dm + cc]     = rtf(o[nt][2] * inv1);
        O[(size_t)rB * Dm + cc + 1] = rtf(o[nt][3] * inv1);
    }
}

// ---------------- router (exact fp32 logits) ----------------------------------
__global__ void route_kernel(const float* __restrict__ H2,
                             const float* __restrict__ SW,
                             const float* __restrict__ SB) {
    int warp = (blockIdx.x * blockDim.x + threadIdx.x) >> 5;
    int lane = threadIdx.x & 31;
    if (warp >= TOK) return;
    const float* hrow = H2 + (size_t)warp * Dm;
    float acc[En];
    #pragma unroll
    for (int e = 0; e < En; e++) acc[e] = 0.f;
    for (int d = lane; d < Dm; d += 32) {
        float hv = hrow[d];
        const float* w = SW + d * En;
        #pragma unroll
        for (int e = 0; e < En; e++) acc[e] += hv * w[e];
    }
    #pragma unroll
    for (int e = 0; e < En; e++)
        #pragma unroll
        for (int o = 16; o; o >>= 1)
            acc[e] += __shfl_xor_sync(0xffffffffu, acc[e], o);
    if (lane == 0) {
        float best = acc[0] + SB[0];
        int be = 0;
        #pragma unroll
        for (int e = 1; e < En; e++) {
            float v = acc[e] + SB[e];
            if (v > best) { best = v; be = e; }
        }
        g_routes[warp] = be;
        atomicAdd(&g_cnt[be], 1);
    }
}

__global__ void offsets_kernel() {
    if (threadIdx.x == 0) {
        int acc = 0;
        for (int e = 0; e < En; e++) { g_off[e] = acc; acc += g_cnt[e]; }
    }
}

__global__ void scatter_kernel() {
    int t = blockIdx.x * blockDim.x + threadIdx.x;
    if (t >= TOK) return;
    int e = g_routes[t];
    int pos = atomicAdd(&g_cur[e], 1);
    g_sorted[g_off[e] + pos] = t;
}

// ---------------- launch ------------------------------------------------------
extern "C" void kernel_launch(void* const* d_in, const int* in_sizes, int n_in,
                              void* d_out, int out_size) {
    const float* x       = (const float*)d_in[0];
    // d_in[1] = indexes_list (unused by reference math)
    const float* ln1_g   = (const float*)d_in[2];
    const float* ln1_b   = (const float*)d_in[3];
    const float* qkv_w   = (const float*)d_in[4];
    const float* proj_w  = (const float*)d_in[5];
    const float* proj_b  = (const float*)d_in[6];
    const float* ln2_g   = (const float*)d_in[7];
    const float* ln2_b   = (const float*)d_in[8];
    const float* sw_w    = (const float*)d_in[9];
    const float* sw_b    = (const float*)d_in[10];
    const float* w1      = (const float*)d_in[11];
    const float* b1      = (const float*)d_in[12];
    const float* w2      = (const float*)d_in[13];
    const float* b2      = (const float*)d_in[14];
    float* out = (float*)d_out;

    float *gh, *gqkv, *go, *gh2, *gy1;
    cudaGetSymbolAddress((void**)&gh,   g_h);
    cudaGetSymbolAddress((void**)&gqkv, g_qkv);
    cudaGetSymbolAddress((void**)&go,   g_o);
    cudaGetSymbolAddress((void**)&gh2,  g_h2);
    cudaGetSymbolAddress((void**)&gy1,  g_y1);

    static int smem_set = 0;
    if (!smem_set) {
        cudaFuncSetAttribute(flash_tf32, cudaFuncAttributeMaxDynamicSharedMemorySize, FA_SMEM);
        cudaFuncSetAttribute(gemm_tf32<false, true>,  cudaFuncAttributeMaxDynamicSharedMemorySize, GEMM_SMEM);
        cudaFuncSetAttribute(gemm_tf32<false, false>, cudaFuncAttributeMaxDynamicSharedMemorySize, GEMM_SMEM);
        cudaFuncSetAttribute(moe1_tf32, cudaFuncAttributeMaxDynamicSharedMemorySize, GEMM_SMEM);
        cudaFuncSetAttribute(moe2_tf32, cudaFuncAttributeMaxDynamicSharedMemorySize, GEMM_SMEM);
        smem_set = 1;
    }

    reset_kernel<<<1, 32>>>();

    // ln1 -> tf32-rounded (feeds qkv GEMM A only)
    ln_kernel<<<TOK, 256>>>(x, ln1_g, ln1_b, gh, 1);
    // qkv = h @ qkv_w, output rounded (feeds flash only)
    gemm_tf32<false, true><<<dim3(2304 / 128, TOK / 128), 256, GEMM_SMEM>>>(
        gh, qkv_w, gqkv, TOK, 2304, Dm, nullptr, nullptr);
    // fused attention; output rounded (feeds proj A only)
    flash_tf32<<<dim3(Sq / 64, BHN), 128, FA_SMEM>>>(gqkv, go);
    // xmid = x + o @ proj_w + proj_b -> d_out (exact fp32: final-output term)
    gemm_tf32<false, false><<<dim3(Dm / 128, TOK / 128), 256, GEMM_SMEM>>>(
        go, proj_w, out, TOK, Dm, Dm, proj_b, x);
    // ln2 -> exact fp32 (router needs exact logits; moe1 cvts in-kernel)
    ln_kernel<<<TOK, 256>>>(out, ln2_g, ln2_b, gh2, 0);
    // routing
    route_kernel<<<512, 256>>>(gh2, sw_w, sw_b);
    offsets_kernel<<<1, 32>>>();
    scatter_kernel<<<TOK / 256, 256>>>();
    // MoE expert GEMMs
    moe1_tf32<<<dim3(FFd / 128, TOK / 128, En), 256, GEMM_SMEM>>>(gh2, w1, b1, gy1);
    moe2_tf32<<<dim3(Dm / 128, TOK / 128, En), 256, GEMM_SMEM>>>(gy1, w2, b2, out);
}